// round 6
// baseline (speedup 1.0000x reference)
#include <cuda_runtime.h>
#include <math.h>

#define BB 256
#define HH 28
#define WW 28

// Scratch (device globals: allocation-free rule). Zero-initialized at module
// load; g_h2p borders are never written by any kernel -> stay zero (padding).
__device__ float g_h1p[BB*30*30*32];   // conv1 out, NHWC padded, zero border
__device__ float g_offs[BB*28*28*18];  // p_conv offsets, NHWC
__device__ float g_h2p[BB*30*30*32];   // deform out, NHWC padded, zero border
__device__ float g_part[BB*7*64];      // partial pooled sums of relu(conv3)

// ---------------------------------------------------------------------------
// K1: conv1(3->32, pad1) + relu + bn1  -> g_h1p (NHWC padded, zero borders)
// ---------------------------------------------------------------------------
__global__ void k1_conv1(const float* __restrict__ x, const float* __restrict__ w1,
                         const float* __restrict__ g1, const float* __restrict__ b1,
                         const float* __restrict__ m1, const float* __restrict__ v1) {
    __shared__ float ws[27*32];          // [c*9+tap][o]
    int tid = threadIdx.x;
    for (int i = tid; i < 27*32; i += blockDim.x) {
        int tap = i >> 5, o = i & 31;
        ws[i] = w1[o*27 + tap];
    }
    __syncthreads();
    int wg   = blockIdx.x*8 + (tid >> 5);
    int lane = tid & 31;
    int b = wg / 900, rem = wg % 900;
    int yp = rem / 30, xp = rem % 30;
    float* dst = &g_h1p[((b*30+yp)*30+xp)*32 + lane];
    if (yp == 0 || yp == 29 || xp == 0 || xp == 29) { *dst = 0.f; return; }
    int y = yp - 1, x0 = xp - 1;
    float acc = 0.f;
    #pragma unroll
    for (int c = 0; c < 3; c++) {
        #pragma unroll
        for (int ky = 0; ky < 3; ky++) {
            int iy = y + ky - 1;
            #pragma unroll
            for (int kx = 0; kx < 3; kx++) {
                int ix = x0 + kx - 1;
                float xv = 0.f;
                if (iy >= 0 && iy < 28 && ix >= 0 && ix < 28)
                    xv = __ldg(&x[((b*3+c)*28+iy)*28+ix]);
                acc = fmaf(xv, ws[(c*9+ky*3+kx)*32 + lane], acc);
            }
        }
    }
    acc = fmaxf(acc, 0.f);
    float inv = g1[lane] * rsqrtf(v1[lane] + 1e-5f);
    *dst = acc * inv + (b1[lane] - m1[lane]*inv);
}

// ---------------------------------------------------------------------------
// K2: p_conv(32->18, pad1) + bias -> g_offs
// block = (image, 4-row strip), 128 thr; 14-px register tile, float4 loads.
// dyn smem: wsh float4[8*9*32] (36864B) + ash 6*30*32 (23040B) = 59904B
// ---------------------------------------------------------------------------
__global__ void __launch_bounds__(128, 3)
k2_pconv(const float* __restrict__ wp, const float* __restrict__ bp) {
    extern __shared__ float sm2[];
    float4* wsh = (float4*)sm2;          // [(c4*9+t)*32 + lane] = w[o=lane][4c4..4c4+3]
    float*  ash = sm2 + 4*8*9*32;        // [ry][x][c], 6x30x32
    int tid = threadIdx.x;
    int b = blockIdx.x / 7, strip = blockIdx.x % 7;
    for (int i = tid; i < 8*9*32; i += 128) {
        int lane = i & 31, t = (i >> 5) % 9, c4 = i / 288;
        if (lane < 18)
            wsh[i] = make_float4(wp[lane*288 + (4*c4+0)*9 + t], wp[lane*288 + (4*c4+1)*9 + t],
                                 wp[lane*288 + (4*c4+2)*9 + t], wp[lane*288 + (4*c4+3)*9 + t]);
        else
            wsh[i] = make_float4(0.f, 0.f, 0.f, 0.f);
    }
    const float4* src = (const float4*)&g_h1p[(b*30 + strip*4)*30*32];
    float4* ash4 = (float4*)ash;
    for (int i = tid; i < 6*30*8; i += 128) ash4[i] = src[i];
    __syncthreads();

    int warp = tid >> 5, lane = tid & 31;
    int y = strip*4 + warp;
    float bpv = (lane < 18) ? bp[lane] : 0.f;
    for (int x0 = 0; x0 < 28; x0 += 14) {
        float acc[14];
        #pragma unroll
        for (int i = 0; i < 14; i++) acc[i] = 0.f;
        for (int t = 0; t < 9; t++) {
            int ty = t/3, tx = t%3;
            const float4* ap = (const float4*)&ash[((warp + ty)*30 + x0 + tx)*32];
            #pragma unroll
            for (int c4 = 0; c4 < 8; c4++) {
                float4 w = wsh[(c4*9+t)*32 + lane];
                #pragma unroll
                for (int i = 0; i < 14; i++) {
                    float4 a = ap[i*8 + c4];
                    acc[i] = fmaf(a.x, w.x, acc[i]);
                    acc[i] = fmaf(a.y, w.y, acc[i]);
                    acc[i] = fmaf(a.z, w.z, acc[i]);
                    acc[i] = fmaf(a.w, w.w, acc[i]);
                }
            }
        }
        if (lane < 18) {
            #pragma unroll
            for (int i = 0; i < 14; i++)
                g_offs[((b*28+y)*28 + x0 + i)*18 + lane] = acc[i] + bpv;
        }
    }
}

// ---------------------------------------------------------------------------
// K3: fused deformable sample + 9pt conv (32->32) + relu + bn2 -> g_h2p
// block = (image, 2-row strip of 56 px), 256 threads.
// Phase A: 8 warps sample 7 px each (lane = in channel) -> xsh[56][288]
// Phase B: float4 x + float4 w loads, scalar FFMA; 7-px tile (lane = out ch)
// dyn smem: wsh float4[72*32] (36864B) + xsh 56*288 (64512B) = 101376B
// ---------------------------------------------------------------------------
__global__ void k3_deform(const float* __restrict__ w2, const float* __restrict__ g2,
                          const float* __restrict__ b2_, const float* __restrict__ m2,
                          const float* __restrict__ v2) {
    extern __shared__ float sm3[];
    float4* wsh = (float4*)sm3;          // [nc4*32 + lane] = w[o=lane][nc4*4 .. +3]
    float*  xsh = sm3 + 9216;            // [pl*288 + n*32 + c]
    int tid = threadIdx.x;
    int b = blockIdx.x / 14, strip = blockIdx.x % 14;
    int y0 = strip*2;
    // xsh index nc = n*32 + c ; weight for (o, nc): w2[o*288 + c*9 + n]
    for (int i = tid; i < 72*32; i += 256) {
        int lane = i & 31, nc4 = i >> 5;
        int n = nc4 >> 3, c = (nc4 & 7)*4;
        wsh[i] = make_float4(w2[lane*288 + (c+0)*9 + n], w2[lane*288 + (c+1)*9 + n],
                             w2[lane*288 + (c+2)*9 + n], w2[lane*288 + (c+3)*9 + n]);
    }
    int warp = tid >> 5, lane = tid & 31;
    const float* img = &g_h1p[b*900*32];

    // Phase A: bilinear sampling
    for (int k = 0; k < 7; k++) {
        int pl = warp + k*8;             // 0..55
        int y = y0 + pl/28, x = pl%28;
        const float* offp = &g_offs[((b*28+y)*28+x)*18];
        #pragma unroll
        for (int n = 0; n < 9; n++) {
            float oy = offp[n];
            float ox = offp[9+n];
            float pyr = (float)(y + n/3) + oy;
            float pxr = (float)(x + n%3) + ox;
            float fy = floorf(pyr), fx = floorf(pxr);
            float qy0 = fminf(fmaxf(fy,       0.f), 29.f);
            float qy1 = fminf(fmaxf(fy + 1.f, 0.f), 29.f);
            float qx0 = fminf(fmaxf(fx,       0.f), 29.f);
            float qx1 = fminf(fmaxf(fx + 1.f, 0.f), 29.f);
            float pyc = fminf(fmaxf(pyr, 0.f), 29.f);
            float pxc = fminf(fmaxf(pxr, 0.f), 29.f);
            float glt = (1.f + (qy0 - pyc)) * (1.f + (qx0 - pxc));
            float grb = (1.f - (qy1 - pyc)) * (1.f - (qx1 - pxc));
            float glb = (1.f + (qy0 - pyc)) * (1.f - (qx1 - pxc));
            float grt = (1.f - (qy1 - pyc)) * (1.f + (qx0 - pxc));
            int iy0 = (int)qy0, iy1 = (int)qy1, ix0 = (int)qx0, ix1 = (int)qx1;
            float v00 = img[(iy0*30+ix0)*32 + lane];
            float v11 = img[(iy1*30+ix1)*32 + lane];
            float v01 = img[(iy0*30+ix1)*32 + lane];
            float v10 = img[(iy1*30+ix0)*32 + lane];
            xsh[pl*288 + n*32 + lane] = glt*v00 + grb*v11 + glb*v01 + grt*v10;
        }
    }
    __syncthreads();

    // Phase B: 288 -> 32 GEMM, float4 k-quads
    int pbase = warp*7;
    float acc[7] = {0,0,0,0,0,0,0};
    const float4* xp0 = (const float4*)&xsh[pbase*288];
    #pragma unroll 4
    for (int nc4 = 0; nc4 < 72; nc4++) {
        float4 w = wsh[nc4*32 + lane];
        #pragma unroll
        for (int i = 0; i < 7; i++) {
            float4 a = xp0[i*72 + nc4];
            acc[i] = fmaf(a.x, w.x, acc[i]);
            acc[i] = fmaf(a.y, w.y, acc[i]);
            acc[i] = fmaf(a.z, w.z, acc[i]);
            acc[i] = fmaf(a.w, w.w, acc[i]);
        }
    }
    float inv = g2[lane] * rsqrtf(v2[lane] + 1e-5f);
    float sh  = b2_[lane] - m2[lane]*inv;
    #pragma unroll
    for (int i = 0; i < 7; i++) {
        int px = pbase + i;
        int y = y0 + px/28, x = px%28;
        g_h2p[((b*30+y+1)*30 + x+1)*32 + lane] = fmaxf(acc[i], 0.f)*inv + sh;
    }
}

// ---------------------------------------------------------------------------
// K4: conv3(32->64, pad1) + relu + partial pooled sum (bn folded into head)
// block = (image, 4-row strip, o-half via blockIdx.y), 128 threads.
// 14-px register tile; 1 weight LDS.128 + 14 broadcast act LDS.128 per
// (t,c4) step with 56 FFMA. smem 59904B -> 3 blocks/SM (12 warps/SM).
// ---------------------------------------------------------------------------
__global__ void __launch_bounds__(128, 3)
k4_conv3(const float* __restrict__ w3) {
    extern __shared__ float sm4[];
    float4* wsh = (float4*)sm4;          // [(c4*9+t)*32+lane] = w[o=obase+lane][4c4..+3]
    float*  ash = sm4 + 4*8*9*32;        // [ry][x][c], 6x30x32
    __shared__ float red[32];
    int tid = threadIdx.x;
    int b = blockIdx.x / 7, strip = blockIdx.x % 7;
    int obase = blockIdx.y * 32;
    for (int i = tid; i < 8*9*32; i += 128) {
        int lane = i & 31, t = (i >> 5) % 9, c4 = i / 288;
        const float* wrow = &w3[(obase + lane)*288];
        wsh[i] = make_float4(wrow[(4*c4+0)*9 + t], wrow[(4*c4+1)*9 + t],
                             wrow[(4*c4+2)*9 + t], wrow[(4*c4+3)*9 + t]);
    }
    const float4* src = (const float4*)&g_h2p[(b*30 + strip*4)*30*32];
    float4* ash4 = (float4*)ash;
    for (int i = tid; i < 6*30*8; i += 128) ash4[i] = src[i];
    if (tid < 32) red[tid] = 0.f;
    __syncthreads();

    int warp = tid >> 5, lane = tid & 31;
    float s0 = 0.f;
    for (int x0 = 0; x0 < 28; x0 += 14) {
        float acc[14];
        #pragma unroll
        for (int i = 0; i < 14; i++) acc[i] = 0.f;
        for (int t = 0; t < 9; t++) {
            int ty = t/3, tx = t%3;
            const float4* ap = (const float4*)&ash[((warp + ty)*30 + x0 + tx)*32];
            #pragma unroll
            for (int c4 = 0; c4 < 8; c4++) {
                float4 w = wsh[(c4*9+t)*32 + lane];
                #pragma unroll
                for (int i = 0; i < 14; i++) {
                    float4 a = ap[i*8 + c4];
                    acc[i] = fmaf(a.x, w.x, acc[i]);
                    acc[i] = fmaf(a.y, w.y, acc[i]);
                    acc[i] = fmaf(a.z, w.z, acc[i]);
                    acc[i] = fmaf(a.w, w.w, acc[i]);
                }
            }
        }
        #pragma unroll
        for (int i = 0; i < 14; i++) s0 += fmaxf(acc[i], 0.f);
    }
    atomicAdd(&red[lane], s0);
    __syncthreads();
    if (tid < 32) g_part[(b*7+strip)*64 + obase + tid] = red[tid];
}

// ---------------------------------------------------------------------------
// K5: reduce partials -> mean -> bn3 -> linear(64->10) -> log_softmax
// ---------------------------------------------------------------------------
__global__ void k5_head(const float* __restrict__ g3, const float* __restrict__ b3,
                        const float* __restrict__ m3, const float* __restrict__ v3,
                        const float* __restrict__ wc, const float* __restrict__ bc,
                        float* __restrict__ out) {
    __shared__ float hsh[64];
    __shared__ float lg[10];
    int b = blockIdx.x, tid = threadIdx.x;
    if (tid < 64) {
        float s = 0.f;
        for (int k = 0; k < 7; k++) s += g_part[(b*7+k)*64 + tid];
        s *= (1.f/784.f);
        float inv = g3[tid] * rsqrtf(v3[tid] + 1e-5f);
        hsh[tid] = s * inv + (b3[tid] - m3[tid]*inv);
    }
    __syncthreads();
    if (tid < 10) {
        float acc = bc[tid];
        for (int o = 0; o < 64; o++) acc = fmaf(hsh[o], wc[tid*64 + o], acc);
        lg[tid] = acc;
    }
    __syncthreads();
    if (tid < 10) {
        float mx = -1e30f;
        for (int j = 0; j < 10; j++) mx = fmaxf(mx, lg[j]);
        float se = 0.f;
        for (int j = 0; j < 10; j++) se += expf(lg[j] - mx);
        out[b*10 + tid] = lg[tid] - mx - logf(se);
    }
}

// ---------------------------------------------------------------------------
extern "C" void kernel_launch(void* const* d_in, const int* in_sizes, int n_in,
                              void* d_out, int out_size) {
    const float* x  = (const float*)d_in[0];
    const float* w1 = (const float*)d_in[1];
    const float* g1 = (const float*)d_in[2];
    const float* b1 = (const float*)d_in[3];
    const float* m1 = (const float*)d_in[4];
    const float* v1 = (const float*)d_in[5];
    const float* wp = (const float*)d_in[6];
    const float* bp = (const float*)d_in[7];
    const float* w2 = (const float*)d_in[8];
    const float* g2 = (const float*)d_in[9];
    const float* b2 = (const float*)d_in[10];
    const float* m2 = (const float*)d_in[11];
    const float* v2 = (const float*)d_in[12];
    const float* w3 = (const float*)d_in[13];
    const float* g3 = (const float*)d_in[14];
    const float* b3 = (const float*)d_in[15];
    const float* m3 = (const float*)d_in[16];
    const float* v3 = (const float*)d_in[17];
    const float* wc = (const float*)d_in[18];
    const float* bc = (const float*)d_in[19];

    cudaFuncSetAttribute(k2_pconv,  cudaFuncAttributeMaxDynamicSharedMemorySize, 59904);
    cudaFuncSetAttribute(k3_deform, cudaFuncAttributeMaxDynamicSharedMemorySize, 101376);
    cudaFuncSetAttribute(k4_conv3,  cudaFuncAttributeMaxDynamicSharedMemorySize, 59904);

    k1_conv1<<<28800, 256>>>(x, w1, g1, b1, m1, v1);
    k2_pconv<<<BB*7, 128, 59904>>>(wp, bp);
    k3_deform<<<BB*14, 256, 101376>>>(w2, g2, b2, m2, v2);
    k4_conv3<<<dim3(BB*7, 2), 128, 59904>>>(w3);
    k5_head<<<BB, 64>>>(g3, b3, m3, v3, wc, bc, (float*)d_out);
}

// round 7
// speedup vs baseline: 1.0613x; 1.0613x over previous
#include <cuda_runtime.h>
#include <math.h>

#define BB 256
#define HH 28
#define WW 28

typedef unsigned long long u64;

// packed f32x2 fma: acc.{lo,hi} += a.{lo,hi} * b.{lo,hi}  (IEEE identical per lane)
__device__ __forceinline__ void ffma2(u64& acc, u64 a, u64 b) {
    asm("fma.rn.f32x2 %0, %1, %2, %0;" : "+l"(acc) : "l"(a), "l"(b));
}
__device__ __forceinline__ float f2sum(u64 v) {
    float lo, hi;
    asm("mov.b64 {%0, %1}, %2;" : "=f"(lo), "=f"(hi) : "l"(v));
    return lo + hi;
}

// Scratch (device globals: allocation-free rule). Zero-initialized at module
// load; g_h2p borders are never written by any kernel -> stay zero (padding).
__device__ float g_h1p[BB*30*30*32];   // conv1 out, NHWC padded, zero border
__device__ float g_offs[BB*28*28*18];  // p_conv offsets, NHWC
__device__ float g_h2p[BB*30*30*32];   // deform out, NHWC padded, zero border
__device__ float g_part[BB*7*64];      // partial pooled sums of relu(conv3)

// ---------------------------------------------------------------------------
// K1: conv1(3->32, pad1) + relu + bn1  -> g_h1p (NHWC padded, zero borders)
// ---------------------------------------------------------------------------
__global__ void k1_conv1(const float* __restrict__ x, const float* __restrict__ w1,
                         const float* __restrict__ g1, const float* __restrict__ b1,
                         const float* __restrict__ m1, const float* __restrict__ v1) {
    __shared__ float ws[27*32];          // [c*9+tap][o]
    int tid = threadIdx.x;
    for (int i = tid; i < 27*32; i += blockDim.x) {
        int tap = i >> 5, o = i & 31;
        ws[i] = w1[o*27 + tap];
    }
    __syncthreads();
    int wg   = blockIdx.x*8 + (tid >> 5);
    int lane = tid & 31;
    int b = wg / 900, rem = wg % 900;
    int yp = rem / 30, xp = rem % 30;
    float* dst = &g_h1p[((b*30+yp)*30+xp)*32 + lane];
    if (yp == 0 || yp == 29 || xp == 0 || xp == 29) { *dst = 0.f; return; }
    int y = yp - 1, x0 = xp - 1;
    float acc = 0.f;
    #pragma unroll
    for (int c = 0; c < 3; c++) {
        #pragma unroll
        for (int ky = 0; ky < 3; ky++) {
            int iy = y + ky - 1;
            #pragma unroll
            for (int kx = 0; kx < 3; kx++) {
                int ix = x0 + kx - 1;
                float xv = 0.f;
                if (iy >= 0 && iy < 28 && ix >= 0 && ix < 28)
                    xv = __ldg(&x[((b*3+c)*28+iy)*28+ix]);
                acc = fmaf(xv, ws[(c*9+ky*3+kx)*32 + lane], acc);
            }
        }
    }
    acc = fmaxf(acc, 0.f);
    float inv = g1[lane] * rsqrtf(v1[lane] + 1e-5f);
    *dst = acc * inv + (b1[lane] - m1[lane]*inv);
}

// ---------------------------------------------------------------------------
// K2: p_conv(32->18, pad1) + bias -> g_offs
// block = (image, 4-row strip), 128 thr. warp = output row, acc[28] tile.
// Per c: 9 scalar weight LDS + 3x30 broadcast act LDS (3-tap sliding window),
// 252 FFMA -> FFMA-bound.
// dyn smem: wsh 9216 floats (36864B) + ash 6*30*32 (23040B) = 59904B
// ---------------------------------------------------------------------------
__global__ void __launch_bounds__(128, 3)
k2_pconv(const float* __restrict__ wp, const float* __restrict__ bp) {
    extern __shared__ float sm2[];
    float* wsh = sm2;                    // [(c*9+t)*32 + lane] = w[o=lane][c][t]
    float* ash = sm2 + 9216;             // [ry][x][c], 6x30x32
    int tid = threadIdx.x;
    int b = blockIdx.x / 7, strip = blockIdx.x % 7;
    for (int i = tid; i < 9216; i += 128) {
        int lane = i & 31, ct = i >> 5;  // ct = c*9+t
        wsh[i] = (lane < 18) ? wp[lane*288 + ct] : 0.f;
    }
    const float4* src = (const float4*)&g_h1p[(b*30 + strip*4)*30*32];
    float4* ash4 = (float4*)ash;
    for (int i = tid; i < 6*30*8; i += 128) ash4[i] = src[i];
    __syncthreads();

    int warp = tid >> 5, lane = tid & 31;
    int y = strip*4 + warp;
    float acc[28];
    #pragma unroll
    for (int i = 0; i < 28; i++) acc[i] = 0.f;

    #pragma unroll 1
    for (int c = 0; c < 32; c++) {
        float wreg[9];
        #pragma unroll
        for (int t = 0; t < 9; t++) wreg[t] = wsh[(c*9+t)*32 + lane];
        #pragma unroll
        for (int ry = 0; ry < 3; ry++) {
            const float* arow = &ash[((warp+ry)*30)*32 + c];
            float w0 = wreg[ry*3], w1 = wreg[ry*3+1], w2 = wreg[ry*3+2];
            float a0 = arow[0], a1 = arow[32];
            #pragma unroll
            for (int xx = 0; xx < 28; xx++) {
                float a2 = arow[(xx+2)*32];
                acc[xx] = fmaf(a0, w0, acc[xx]);
                acc[xx] = fmaf(a1, w1, acc[xx]);
                acc[xx] = fmaf(a2, w2, acc[xx]);
                a0 = a1; a1 = a2;
            }
        }
    }
    if (lane < 18) {
        float bpv = bp[lane];
        #pragma unroll
        for (int i = 0; i < 28; i++)
            g_offs[((b*28+y)*28 + i)*18 + lane] = acc[i] + bpv;
    }
}

// ---------------------------------------------------------------------------
// K3: fused deformable sample + 9pt conv (32->32) + relu + bn2 -> g_h2p
// block = (image, 2-row strip of 56 px), 256 threads.
// Phase A: 8 warps sample 7 px each (lane = in channel) -> xsh[56][288]
// Phase B: k-pair f32x2 GEMM; LDS.64 act (broadcast) + LDS.64 weight pairs.
// dyn smem: wsh2 float2[144*32] (36864B) + xsh 56*288 (64512B) = 101376B
// ---------------------------------------------------------------------------
__global__ void k3_deform(const float* __restrict__ w2, const float* __restrict__ g2,
                          const float* __restrict__ b2_, const float* __restrict__ m2,
                          const float* __restrict__ v2) {
    extern __shared__ float sm3[];
    float2* wsh = (float2*)sm3;          // [j*32 + lane] = (w[k=2j][o=lane], w[k=2j+1][o=lane])
    float*  xsh = sm3 + 9216;            // [pl*288 + n*32 + c]
    int tid = threadIdx.x;
    int b = blockIdx.x / 14, strip = blockIdx.x % 14;
    int y0 = strip*2;
    // k index = n*32 + c ; weight for (o, k): w2[o*288 + c*9 + n]
    for (int i = tid; i < 144*32; i += 256) {
        int lane = i & 31, j = i >> 5;
        int n = j >> 4, c = (2*j) & 31;
        wsh[i] = make_float2(w2[lane*288 + c*9 + n], w2[lane*288 + (c+1)*9 + n]);
    }
    int warp = tid >> 5, lane = tid & 31;
    const float* img = &g_h1p[b*900*32];

    // Phase A: bilinear sampling
    for (int k = 0; k < 7; k++) {
        int pl = warp + k*8;             // 0..55
        int y = y0 + pl/28, x = pl%28;
        const float* offp = &g_offs[((b*28+y)*28+x)*18];
        #pragma unroll
        for (int n = 0; n < 9; n++) {
            float oy = offp[n];
            float ox = offp[9+n];
            float pyr = (float)(y + n/3) + oy;
            float pxr = (float)(x + n%3) + ox;
            float fy = floorf(pyr), fx = floorf(pxr);
            float qy0 = fminf(fmaxf(fy,       0.f), 29.f);
            float qy1 = fminf(fmaxf(fy + 1.f, 0.f), 29.f);
            float qx0 = fminf(fmaxf(fx,       0.f), 29.f);
            float qx1 = fminf(fmaxf(fx + 1.f, 0.f), 29.f);
            float pyc = fminf(fmaxf(pyr, 0.f), 29.f);
            float pxc = fminf(fmaxf(pxr, 0.f), 29.f);
            float glt = (1.f + (qy0 - pyc)) * (1.f + (qx0 - pxc));
            float grb = (1.f - (qy1 - pyc)) * (1.f - (qx1 - pxc));
            float glb = (1.f + (qy0 - pyc)) * (1.f - (qx1 - pxc));
            float grt = (1.f - (qy1 - pyc)) * (1.f + (qx0 - pxc));
            int iy0 = (int)qy0, iy1 = (int)qy1, ix0 = (int)qx0, ix1 = (int)qx1;
            float v00 = img[(iy0*30+ix0)*32 + lane];
            float v11 = img[(iy1*30+ix1)*32 + lane];
            float v01 = img[(iy0*30+ix1)*32 + lane];
            float v10 = img[(iy1*30+ix0)*32 + lane];
            xsh[pl*288 + n*32 + lane] = glt*v00 + grb*v11 + glb*v01 + grt*v10;
        }
    }
    __syncthreads();

    // Phase B: 288 -> 32 GEMM, k-pairs via f32x2
    int pbase = warp*7;
    u64 acc2[7] = {0,0,0,0,0,0,0};
    const float* xp0 = &xsh[pbase*288];
    #pragma unroll 2
    for (int j = 0; j < 144; j++) {
        u64 wv = *(const u64*)&wsh[j*32 + lane];
        #pragma unroll
        for (int i = 0; i < 7; i++) {
            u64 a = *(const u64*)(xp0 + i*288 + 2*j);
            ffma2(acc2[i], a, wv);
        }
    }
    float inv = g2[lane] * rsqrtf(v2[lane] + 1e-5f);
    float sh  = b2_[lane] - m2[lane]*inv;
    #pragma unroll
    for (int i = 0; i < 7; i++) {
        int px = pbase + i;
        int y = y0 + px/28, x = px%28;
        g_h2p[((b*30+y+1)*30 + x+1)*32 + lane] = fmaxf(f2sum(acc2[i]), 0.f)*inv + sh;
    }
}

// ---------------------------------------------------------------------------
// K4: conv3(32->64, pad1) + relu + partial pooled sum (bn folded into head)
// block = (image, 4-row strip, o-half via blockIdx.y), 128 threads.
// warp = output row, acc[28] register tile, 3-tap sliding act window.
// Per c: 9 scalar weight LDS + 90 broadcast act LDS + 252 FFMA -> FFMA-bound.
// dyn smem: wsh 9216 floats (36864B) + ash 6*30*32 (23040B) = 59904B -> 3 blk/SM
// ---------------------------------------------------------------------------
__global__ void __launch_bounds__(128, 3)
k4_conv3(const float* __restrict__ w3) {
    extern __shared__ float sm4[];
    float* wsh = sm4;                    // [(c*9+t)*32 + lane] = w[o=obase+lane][c][t]
    float* ash = sm4 + 9216;             // [ry][x][c], 6x30x32
    __shared__ float red[32];
    int tid = threadIdx.x;
    int b = blockIdx.x / 7, strip = blockIdx.x % 7;
    int obase = blockIdx.y * 32;
    for (int i = tid; i < 9216; i += 128) {
        int lane = i & 31, ct = i >> 5;  // ct = c*9+t
        wsh[i] = w3[(obase + lane)*288 + ct];
    }
    const float4* src = (const float4*)&g_h2p[(b*30 + strip*4)*30*32];
    float4* ash4 = (float4*)ash;
    for (int i = tid; i < 6*30*8; i += 128) ash4[i] = src[i];
    if (tid < 32) red[tid] = 0.f;
    __syncthreads();

    int warp = tid >> 5, lane = tid & 31;
    float acc[28];
    #pragma unroll
    for (int i = 0; i < 28; i++) acc[i] = 0.f;

    #pragma unroll 1
    for (int c = 0; c < 32; c++) {
        float wreg[9];
        #pragma unroll
        for (int t = 0; t < 9; t++) wreg[t] = wsh[(c*9+t)*32 + lane];
        #pragma unroll
        for (int ry = 0; ry < 3; ry++) {
            const float* arow = &ash[((warp+ry)*30)*32 + c];
            float w0 = wreg[ry*3], w1 = wreg[ry*3+1], w2 = wreg[ry*3+2];
            float a0 = arow[0], a1 = arow[32];
            #pragma unroll
            for (int xx = 0; xx < 28; xx++) {
                float a2 = arow[(xx+2)*32];
                acc[xx] = fmaf(a0, w0, acc[xx]);
                acc[xx] = fmaf(a1, w1, acc[xx]);
                acc[xx] = fmaf(a2, w2, acc[xx]);
                a0 = a1; a1 = a2;
            }
        }
    }
    float s0 = 0.f;
    #pragma unroll
    for (int i = 0; i < 28; i++) s0 += fmaxf(acc[i], 0.f);
    atomicAdd(&red[lane], s0);
    __syncthreads();
    if (tid < 32) g_part[(b*7+strip)*64 + obase + tid] = red[tid];
}

// ---------------------------------------------------------------------------
// K5: reduce partials -> mean -> bn3 -> linear(64->10) -> log_softmax
// ---------------------------------------------------------------------------
__global__ void k5_head(const float* __restrict__ g3, const float* __restrict__ b3,
                        const float* __restrict__ m3, const float* __restrict__ v3,
                        const float* __restrict__ wc, const float* __restrict__ bc,
                        float* __restrict__ out) {
    __shared__ float hsh[64];
    __shared__ float lg[10];
    int b = blockIdx.x, tid = threadIdx.x;
    if (tid < 64) {
        float s = 0.f;
        for (int k = 0; k < 7; k++) s += g_part[(b*7+k)*64 + tid];
        s *= (1.f/784.f);
        float inv = g3[tid] * rsqrtf(v3[tid] + 1e-5f);
        hsh[tid] = s * inv + (b3[tid] - m3[tid]*inv);
    }
    __syncthreads();
    if (tid < 10) {
        float acc = bc[tid];
        for (int o = 0; o < 64; o++) acc = fmaf(hsh[o], wc[tid*64 + o], acc);
        lg[tid] = acc;
    }
    __syncthreads();
    if (tid < 10) {
        float mx = -1e30f;
        for (int j = 0; j < 10; j++) mx = fmaxf(mx, lg[j]);
        float se = 0.f;
        for (int j = 0; j < 10; j++) se += expf(lg[j] - mx);
        out[b*10 + tid] = lg[tid] - mx - logf(se);
    }
}

// ---------------------------------------------------------------------------
extern "C" void kernel_launch(void* const* d_in, const int* in_sizes, int n_in,
                              void* d_out, int out_size) {
    const float* x  = (const float*)d_in[0];
    const float* w1 = (const float*)d_in[1];
    const float* g1 = (const float*)d_in[2];
    const float* b1 = (const float*)d_in[3];
    const float* m1 = (const float*)d_in[4];
    const float* v1 = (const float*)d_in[5];
    const float* wp = (const float*)d_in[6];
    const float* bp = (const float*)d_in[7];
    const float* w2 = (const float*)d_in[8];
    const float* g2 = (const float*)d_in[9];
    const float* b2 = (const float*)d_in[10];
    const float* m2 = (const float*)d_in[11];
    const float* v2 = (const float*)d_in[12];
    const float* w3 = (const float*)d_in[13];
    const float* g3 = (const float*)d_in[14];
    const float* b3 = (const float*)d_in[15];
    const float* m3 = (const float*)d_in[16];
    const float* v3 = (const float*)d_in[17];
    const float* wc = (const float*)d_in[18];
    const float* bc = (const float*)d_in[19];

    cudaFuncSetAttribute(k2_pconv,  cudaFuncAttributeMaxDynamicSharedMemorySize, 59904);
    cudaFuncSetAttribute(k3_deform, cudaFuncAttributeMaxDynamicSharedMemorySize, 101376);
    cudaFuncSetAttribute(k4_conv3,  cudaFuncAttributeMaxDynamicSharedMemorySize, 59904);

    k1_conv1<<<28800, 256>>>(x, w1, g1, b1, m1, v1);
    k2_pconv<<<BB*7, 128, 59904>>>(wp, bp);
    k3_deform<<<BB*14, 256, 101376>>>(w2, g2, b2, m2, v2);
    k4_conv3<<<dim3(BB*7, 2), 128, 59904>>>(w3);
    k5_head<<<BB, 64>>>(g3, b3, m3, v3, wc, bc, (float*)d_out);
}

// round 8
// speedup vs baseline: 1.1303x; 1.0651x over previous
#include <cuda_runtime.h>
#include <math.h>

#define BB 256
#define HH 28
#define WW 28

typedef unsigned long long u64;

// packed f32x2 fma: acc.{lo,hi} += a.{lo,hi} * b.{lo,hi}  (IEEE identical per lane)
__device__ __forceinline__ void ffma2(u64& acc, u64 a, u64 b) {
    asm("fma.rn.f32x2 %0, %1, %2, %0;" : "+l"(acc) : "l"(a), "l"(b));
}
__device__ __forceinline__ float f2sum(u64 v) {
    float lo, hi;
    asm("mov.b64 {%0, %1}, %2;" : "=f"(lo), "=f"(hi) : "l"(v));
    return lo + hi;
}

// Scratch (device globals: allocation-free rule). Zero-initialized at module
// load; g_h2p borders are never written by any kernel -> stay zero (padding).
__device__ float g_h1p[BB*30*30*32];   // conv1 out, NHWC padded, zero border
__device__ float g_offs[BB*28*28*18];  // p_conv offsets, NHWC
__device__ float g_h2p[BB*30*30*32];   // deform out, NHWC padded, zero border
__device__ float g_part[BB*7*64];      // partial pooled sums of relu(conv3)

// ---------------------------------------------------------------------------
// K1: conv1(3->32, pad1) + relu + bn1  -> g_h1p (NHWC padded, zero borders)
// ---------------------------------------------------------------------------
__global__ void k1_conv1(const float* __restrict__ x, const float* __restrict__ w1,
                         const float* __restrict__ g1, const float* __restrict__ b1,
                         const float* __restrict__ m1, const float* __restrict__ v1) {
    __shared__ float ws[27*32];          // [c*9+tap][o]
    int tid = threadIdx.x;
    for (int i = tid; i < 27*32; i += blockDim.x) {
        int tap = i >> 5, o = i & 31;
        ws[i] = w1[o*27 + tap];
    }
    __syncthreads();
    int wg   = blockIdx.x*8 + (tid >> 5);
    int lane = tid & 31;
    int b = wg / 900, rem = wg % 900;
    int yp = rem / 30, xp = rem % 30;
    float* dst = &g_h1p[((b*30+yp)*30+xp)*32 + lane];
    if (yp == 0 || yp == 29 || xp == 0 || xp == 29) { *dst = 0.f; return; }
    int y = yp - 1, x0 = xp - 1;
    float acc = 0.f;
    #pragma unroll
    for (int c = 0; c < 3; c++) {
        #pragma unroll
        for (int ky = 0; ky < 3; ky++) {
            int iy = y + ky - 1;
            #pragma unroll
            for (int kx = 0; kx < 3; kx++) {
                int ix = x0 + kx - 1;
                float xv = 0.f;
                if (iy >= 0 && iy < 28 && ix >= 0 && ix < 28)
                    xv = __ldg(&x[((b*3+c)*28+iy)*28+ix]);
                acc = fmaf(xv, ws[(c*9+ky*3+kx)*32 + lane], acc);
            }
        }
    }
    acc = fmaxf(acc, 0.f);
    float inv = g1[lane] * rsqrtf(v1[lane] + 1e-5f);
    *dst = acc * inv + (b1[lane] - m1[lane]*inv);
}

// ---------------------------------------------------------------------------
// K2: p_conv(32->18, pad1) + bias -> g_offs
// block = (image, 4-row strip), 128 thr. warp = output row, acc2[28] u64 tile.
// c-pair f32x2: per c2, 9 LDS.64 weights + 90 LDS.64 acts (sliding window),
// 252 FFMA2.
// dyn smem: wsh2 float2[16*9*32] (36864B) + ash 6*30*32 (23040B) = 59904B
// ---------------------------------------------------------------------------
__global__ void __launch_bounds__(128, 3)
k2_pconv(const float* __restrict__ wp, const float* __restrict__ bp) {
    extern __shared__ float sm2[];
    float2* wsh = (float2*)sm2;          // [(c2*9+t)*32+lane] = (w[o=lane][2c2][t], w[o=lane][2c2+1][t])
    float*  ash = sm2 + 9216;            // [ry][x][c], 6x30x32
    int tid = threadIdx.x;
    int b = blockIdx.x / 7, strip = blockIdx.x % 7;
    for (int i = tid; i < 16*9*32; i += 128) {
        int lane = i & 31, t = (i >> 5) % 9, c2 = i / 288;
        if (lane < 18)
            wsh[i] = make_float2(wp[lane*288 + (2*c2)*9 + t], wp[lane*288 + (2*c2+1)*9 + t]);
        else
            wsh[i] = make_float2(0.f, 0.f);
    }
    const float4* src = (const float4*)&g_h1p[(b*30 + strip*4)*30*32];
    float4* ash4 = (float4*)ash;
    for (int i = tid; i < 6*30*8; i += 128) ash4[i] = src[i];
    __syncthreads();

    int warp = tid >> 5, lane = tid & 31;
    int y = strip*4 + warp;
    u64 acc2[28];
    #pragma unroll
    for (int i = 0; i < 28; i++) acc2[i] = 0ull;

    #pragma unroll 1
    for (int c2 = 0; c2 < 16; c2++) {
        u64 wreg[9];
        #pragma unroll
        for (int t = 0; t < 9; t++) wreg[t] = *(const u64*)&wsh[(c2*9+t)*32 + lane];
        #pragma unroll
        for (int ry = 0; ry < 3; ry++) {
            const u64* arow = (const u64*)&ash[((warp+ry)*30)*32 + 2*c2];  // stride 16 u64 per x
            u64 w0 = wreg[ry*3], w1 = wreg[ry*3+1], w2 = wreg[ry*3+2];
            u64 a0 = arow[0], a1 = arow[16];
            #pragma unroll
            for (int xx = 0; xx < 28; xx++) {
                u64 a2 = arow[(xx+2)*16];
                ffma2(acc2[xx], a0, w0);
                ffma2(acc2[xx], a1, w1);
                ffma2(acc2[xx], a2, w2);
                a0 = a1; a1 = a2;
            }
        }
    }
    if (lane < 18) {
        float bpv = bp[lane];
        #pragma unroll
        for (int i = 0; i < 28; i++)
            g_offs[((b*28+y)*28 + i)*18 + lane] = f2sum(acc2[i]) + bpv;
    }
}

// ---------------------------------------------------------------------------
// K3: fused deformable sample + 9pt conv (32->32) + relu + bn2 -> g_h2p
// block = (image, 2-row strip of 56 px), 256 threads.
// Phase A: 8 warps sample 7 px each (lane = in channel) -> xsh[56][288]
// Phase B: k-pair f32x2 GEMM; LDS.64 act (broadcast) + LDS.64 weight pairs.
// dyn smem: wsh2 float2[144*32] (36864B) + xsh 56*288 (64512B) = 101376B
// ---------------------------------------------------------------------------
__global__ void k3_deform(const float* __restrict__ w2, const float* __restrict__ g2,
                          const float* __restrict__ b2_, const float* __restrict__ m2,
                          const float* __restrict__ v2) {
    extern __shared__ float sm3[];
    float2* wsh = (float2*)sm3;          // [j*32 + lane] = (w[k=2j][o=lane], w[k=2j+1][o=lane])
    float*  xsh = sm3 + 9216;            // [pl*288 + n*32 + c]
    int tid = threadIdx.x;
    int b = blockIdx.x / 14, strip = blockIdx.x % 14;
    int y0 = strip*2;
    // k index = n*32 + c ; weight for (o, k): w2[o*288 + c*9 + n]
    for (int i = tid; i < 144*32; i += 256) {
        int lane = i & 31, j = i >> 5;
        int n = j >> 4, c = (2*j) & 31;
        wsh[i] = make_float2(w2[lane*288 + c*9 + n], w2[lane*288 + (c+1)*9 + n]);
    }
    int warp = tid >> 5, lane = tid & 31;
    const float* img = &g_h1p[b*900*32];

    // Phase A: bilinear sampling
    for (int k = 0; k < 7; k++) {
        int pl = warp + k*8;             // 0..55
        int y = y0 + pl/28, x = pl%28;
        const float* offp = &g_offs[((b*28+y)*28+x)*18];
        #pragma unroll
        for (int n = 0; n < 9; n++) {
            float oy = offp[n];
            float ox = offp[9+n];
            float pyr = (float)(y + n/3) + oy;
            float pxr = (float)(x + n%3) + ox;
            float fy = floorf(pyr), fx = floorf(pxr);
            float qy0 = fminf(fmaxf(fy,       0.f), 29.f);
            float qy1 = fminf(fmaxf(fy + 1.f, 0.f), 29.f);
            float qx0 = fminf(fmaxf(fx,       0.f), 29.f);
            float qx1 = fminf(fmaxf(fx + 1.f, 0.f), 29.f);
            float pyc = fminf(fmaxf(pyr, 0.f), 29.f);
            float pxc = fminf(fmaxf(pxr, 0.f), 29.f);
            float glt = (1.f + (qy0 - pyc)) * (1.f + (qx0 - pxc));
            float grb = (1.f - (qy1 - pyc)) * (1.f - (qx1 - pxc));
            float glb = (1.f + (qy0 - pyc)) * (1.f - (qx1 - pxc));
            float grt = (1.f - (qy1 - pyc)) * (1.f + (qx0 - pxc));
            int iy0 = (int)qy0, iy1 = (int)qy1, ix0 = (int)qx0, ix1 = (int)qx1;
            float v00 = img[(iy0*30+ix0)*32 + lane];
            float v11 = img[(iy1*30+ix1)*32 + lane];
            float v01 = img[(iy0*30+ix1)*32 + lane];
            float v10 = img[(iy1*30+ix0)*32 + lane];
            xsh[pl*288 + n*32 + lane] = glt*v00 + grb*v11 + glb*v01 + grt*v10;
        }
    }
    __syncthreads();

    // Phase B: 288 -> 32 GEMM, k-pairs via f32x2
    int pbase = warp*7;
    u64 acc2[7] = {0,0,0,0,0,0,0};
    const float* xp0 = &xsh[pbase*288];
    #pragma unroll 2
    for (int j = 0; j < 144; j++) {
        u64 wv = *(const u64*)&wsh[j*32 + lane];
        #pragma unroll
        for (int i = 0; i < 7; i++) {
            u64 a = *(const u64*)(xp0 + i*288 + 2*j);
            ffma2(acc2[i], a, wv);
        }
    }
    float inv = g2[lane] * rsqrtf(v2[lane] + 1e-5f);
    float sh  = b2_[lane] - m2[lane]*inv;
    #pragma unroll
    for (int i = 0; i < 7; i++) {
        int px = pbase + i;
        int y = y0 + px/28, x = px%28;
        g_h2p[((b*30+y+1)*30 + x+1)*32 + lane] = fmaxf(f2sum(acc2[i]), 0.f)*inv + sh;
    }
}

// ---------------------------------------------------------------------------
// K4: conv3(32->64, pad1) + relu + partial pooled sum (bn folded into head)
// block = (image, 4-row strip, o-half via blockIdx.y), 128 threads.
// warp = output row, acc2[28] u64 tile, c-pair f32x2 + 3-tap sliding window.
// Per c2: 9 LDS.64 weights + 90 LDS.64 acts + 252 FFMA2.
// dyn smem: wsh2 float2[16*9*32] (36864B) + ash 6*30*32 (23040B) = 59904B
// ---------------------------------------------------------------------------
__global__ void __launch_bounds__(128, 3)
k4_conv3(const float* __restrict__ w3) {
    extern __shared__ float sm4[];
    float2* wsh = (float2*)sm4;          // [(c2*9+t)*32+lane] = (w[o][2c2][t], w[o][2c2+1][t])
    float*  ash = sm4 + 9216;            // [ry][x][c], 6x30x32
    __shared__ float red[32];
    int tid = threadIdx.x;
    int b = blockIdx.x / 7, strip = blockIdx.x % 7;
    int obase = blockIdx.y * 32;
    for (int i = tid; i < 16*9*32; i += 128) {
        int lane = i & 31, t = (i >> 5) % 9, c2 = i / 288;
        const float* wrow = &w3[(obase + lane)*288];
        wsh[i] = make_float2(wrow[(2*c2)*9 + t], wrow[(2*c2+1)*9 + t]);
    }
    const float4* src = (const float4*)&g_h2p[(b*30 + strip*4)*30*32];
    float4* ash4 = (float4*)ash;
    for (int i = tid; i < 6*30*8; i += 128) ash4[i] = src[i];
    if (tid < 32) red[tid] = 0.f;
    __syncthreads();

    int warp = tid >> 5, lane = tid & 31;
    u64 acc2[28];
    #pragma unroll
    for (int i = 0; i < 28; i++) acc2[i] = 0ull;

    #pragma unroll 1
    for (int c2 = 0; c2 < 16; c2++) {
        u64 wreg[9];
        #pragma unroll
        for (int t = 0; t < 9; t++) wreg[t] = *(const u64*)&wsh[(c2*9+t)*32 + lane];
        #pragma unroll
        for (int ry = 0; ry < 3; ry++) {
            const u64* arow = (const u64*)&ash[((warp+ry)*30)*32 + 2*c2];  // stride 16 u64 per x
            u64 w0 = wreg[ry*3], w1 = wreg[ry*3+1], w2 = wreg[ry*3+2];
            u64 a0 = arow[0], a1 = arow[16];
            #pragma unroll
            for (int xx = 0; xx < 28; xx++) {
                u64 a2 = arow[(xx+2)*16];
                ffma2(acc2[xx], a0, w0);
                ffma2(acc2[xx], a1, w1);
                ffma2(acc2[xx], a2, w2);
                a0 = a1; a1 = a2;
            }
        }
    }
    float s0 = 0.f;
    #pragma unroll
    for (int i = 0; i < 28; i++) s0 += fmaxf(f2sum(acc2[i]), 0.f);
    atomicAdd(&red[lane], s0);
    __syncthreads();
    if (tid < 32) g_part[(b*7+strip)*64 + obase + tid] = red[tid];
}

// ---------------------------------------------------------------------------
// K5: reduce partials -> mean -> bn3 -> linear(64->10) -> log_softmax
// ---------------------------------------------------------------------------
__global__ void k5_head(const float* __restrict__ g3, const float* __restrict__ b3,
                        const float* __restrict__ m3, const float* __restrict__ v3,
                        const float* __restrict__ wc, const float* __restrict__ bc,
                        float* __restrict__ out) {
    __shared__ float hsh[64];
    __shared__ float lg[10];
    int b = blockIdx.x, tid = threadIdx.x;
    if (tid < 64) {
        float s = 0.f;
        for (int k = 0; k < 7; k++) s += g_part[(b*7+k)*64 + tid];
        s *= (1.f/784.f);
        float inv = g3[tid] * rsqrtf(v3[tid] + 1e-5f);
        hsh[tid] = s * inv + (b3[tid] - m3[tid]*inv);
    }
    __syncthreads();
    if (tid < 10) {
        float acc = bc[tid];
        for (int o = 0; o < 64; o++) acc = fmaf(hsh[o], wc[tid*64 + o], acc);
        lg[tid] = acc;
    }
    __syncthreads();
    if (tid < 10) {
        float mx = -1e30f;
        for (int j = 0; j < 10; j++) mx = fmaxf(mx, lg[j]);
        float se = 0.f;
        for (int j = 0; j < 10; j++) se += expf(lg[j] - mx);
        out[b*10 + tid] = lg[tid] - mx - logf(se);
    }
}

// ---------------------------------------------------------------------------
extern "C" void kernel_launch(void* const* d_in, const int* in_sizes, int n_in,
                              void* d_out, int out_size) {
    const float* x  = (const float*)d_in[0];
    const float* w1 = (const float*)d_in[1];
    const float* g1 = (const float*)d_in[2];
    const float* b1 = (const float*)d_in[3];
    const float* m1 = (const float*)d_in[4];
    const float* v1 = (const float*)d_in[5];
    const float* wp = (const float*)d_in[6];
    const float* bp = (const float*)d_in[7];
    const float* w2 = (const float*)d_in[8];
    const float* g2 = (const float*)d_in[9];
    const float* b2 = (const float*)d_in[10];
    const float* m2 = (const float*)d_in[11];
    const float* v2 = (const float*)d_in[12];
    const float* w3 = (const float*)d_in[13];
    const float* g3 = (const float*)d_in[14];
    const float* b3 = (const float*)d_in[15];
    const float* m3 = (const float*)d_in[16];
    const float* v3 = (const float*)d_in[17];
    const float* wc = (const float*)d_in[18];
    const float* bc = (const float*)d_in[19];

    cudaFuncSetAttribute(k2_pconv,  cudaFuncAttributeMaxDynamicSharedMemorySize, 59904);
    cudaFuncSetAttribute(k3_deform, cudaFuncAttributeMaxDynamicSharedMemorySize, 101376);
    cudaFuncSetAttribute(k4_conv3,  cudaFuncAttributeMaxDynamicSharedMemorySize, 59904);

    k1_conv1<<<28800, 256>>>(x, w1, g1, b1, m1, v1);
    k2_pconv<<<BB*7, 128, 59904>>>(wp, bp);
    k3_deform<<<BB*14, 256, 101376>>>(w2, g2, b2, m2, v2);
    k4_conv3<<<dim3(BB*7, 2), 128, 59904>>>(w3);
    k5_head<<<BB, 64>>>(g3, b3, m3, v3, wc, bc, (float*)d_out);
}

// round 9
// speedup vs baseline: 1.1694x; 1.0345x over previous
#include <cuda_runtime.h>
#include <math.h>

#define BB 256
#define HH 28
#define WW 28

typedef unsigned long long u64;

// packed f32x2 fma: acc.{lo,hi} += a.{lo,hi} * b.{lo,hi}  (IEEE identical per lane)
__device__ __forceinline__ void ffma2(u64& acc, u64 a, u64 b) {
    asm("fma.rn.f32x2 %0, %1, %2, %0;" : "+l"(acc) : "l"(a), "l"(b));
}
__device__ __forceinline__ float f2sum(u64 v) {
    float lo, hi;
    asm("mov.b64 {%0, %1}, %2;" : "=f"(lo), "=f"(hi) : "l"(v));
    return lo + hi;
}

// Scratch (device globals: allocation-free rule). Zero-initialized at module
// load; padded borders of g_h1p/g_h2p are never written -> stay zero.
__device__ float g_h1p[BB*30*30*32];   // conv1 out, NHWC padded, zero border
__device__ float g_offs[BB*28*28*18];  // p_conv offsets, NHWC
__device__ float g_h2p[BB*30*30*32];   // deform out, NHWC padded, zero border
__device__ float g_part[BB*7*64];      // partial pooled sums of relu(conv3)

// ---------------------------------------------------------------------------
// K1: conv1(3->32, pad1) + relu + bn1 -> g_h1p interior (borders stay 0)
// block = image, 256 thr (8 warps); warp does rows r, r+8, ... lane = o.
// Input staged zero-padded 3x30x30 in smem; sliding 3-tap window.
// ---------------------------------------------------------------------------
__global__ void k1_conv1(const float* __restrict__ x, const float* __restrict__ w1,
                         const float* __restrict__ g1, const float* __restrict__ b1,
                         const float* __restrict__ m1, const float* __restrict__ v1) {
    __shared__ float xs[3*30*30];        // [c][yp][xp], zero borders
    __shared__ float ws[27*32];          // [c*9+t][o]
    int tid = threadIdx.x;
    int b = blockIdx.x;
    for (int i = tid; i < 2700; i += 256) xs[i] = 0.f;
    for (int i = tid; i < 27*32; i += 256) {
        int t = i >> 5, o = i & 31;
        ws[i] = w1[o*27 + t];
    }
    __syncthreads();
    for (int i = tid; i < 3*28*28; i += 256) {
        int c = i / 784, rem = i % 784;
        int y = rem / 28, xx = rem % 28;
        xs[c*900 + (y+1)*30 + xx+1] = x[b*2352 + i];
    }
    __syncthreads();

    int warp = tid >> 5, lane = tid & 31;
    float inv = g1[lane] * rsqrtf(v1[lane] + 1e-5f);
    float sh  = b1[lane] - m1[lane]*inv;

    for (int y = warp; y < 28; y += 8) {
        float acc[28];
        #pragma unroll
        for (int i = 0; i < 28; i++) acc[i] = 0.f;
        #pragma unroll
        for (int c = 0; c < 3; c++) {
            #pragma unroll
            for (int ky = 0; ky < 3; ky++) {
                const float* arow = &xs[c*900 + (y+ky)*30];
                float w0 = ws[(c*9+ky*3+0)*32 + lane];
                float w1v = ws[(c*9+ky*3+1)*32 + lane];
                float w2 = ws[(c*9+ky*3+2)*32 + lane];
                float a0 = arow[0], a1 = arow[1];
                #pragma unroll
                for (int xx = 0; xx < 28; xx++) {
                    float a2 = arow[xx+2];
                    acc[xx] = fmaf(a0, w0, acc[xx]);
                    acc[xx] = fmaf(a1, w1v, acc[xx]);
                    acc[xx] = fmaf(a2, w2, acc[xx]);
                    a0 = a1; a1 = a2;
                }
            }
        }
        #pragma unroll
        for (int xx = 0; xx < 28; xx++)
            g_h1p[((b*30+y+1)*30 + xx+1)*32 + lane] = fmaxf(acc[xx], 0.f)*inv + sh;
    }
}

// ---------------------------------------------------------------------------
// K2: p_conv(32->18, pad1) + bias -> g_offs
// block = (image, 4-row strip), 128 thr; warp = row; lane = (xg4, og8);
// thread tile 7px x 4o, c-pair f32x2, lane-distributed operands.
// acts padded to 36 floats/px for bank-disjoint 4-address LDS.64.
// dyn smem: wsh u64[16*9*32] (36864B) + ash 6*30*36 floats (25920B) = 62784B
// ---------------------------------------------------------------------------
__global__ void __launch_bounds__(128, 3)
k2_pconv(const float* __restrict__ wp, const float* __restrict__ bp) {
    extern __shared__ float sm2[];
    u64*   wsh = (u64*)sm2;              // [(c2*9+t)*32 + o] = (w[o][2c2][t], w[o][2c2+1][t])
    float* ash = sm2 + 9216;             // [ry][x*36 + c], 6 rows x 30 px
    int tid = threadIdx.x;
    int b = blockIdx.x / 7, strip = blockIdx.x % 7;
    for (int i = tid; i < 4608; i += 128) {
        int o = i & 31, t = (i >> 5) % 9, c2 = i / 288;
        float lo = 0.f, hi = 0.f;
        if (o < 18) {
            const float* wr = &wp[o*288];
            lo = wr[(2*c2)*9 + t]; hi = wr[(2*c2+1)*9 + t];
        }
        ((float2*)wsh)[i] = make_float2(lo, hi);
    }
    const float4* src = (const float4*)&g_h1p[(b*30 + strip*4)*30*32];
    for (int i = tid; i < 6*30*8; i += 128) {
        int q = i & 7, px = (i >> 3) % 30, ry = i / 240;
        *(float4*)&ash[ry*1080 + px*36 + q*4] = src[i];
    }
    __syncthreads();

    int warp = tid >> 5, lane = tid & 31;
    int xg = lane >> 3, og = lane & 7;
    int x0 = xg * 7;
    int y = strip*4 + warp;
    u64 acc[28];                         // [xx*4 + oo]
    #pragma unroll
    for (int i = 0; i < 28; i++) acc[i] = 0ull;

    #pragma unroll 1
    for (int c2 = 0; c2 < 16; c2++) {
        #pragma unroll
        for (int ky = 0; ky < 3; ky++) {
            const float* arow = &ash[(warp+ky)*1080 + x0*36 + 2*c2];
            u64 win[9];
            #pragma unroll
            for (int k = 0; k < 9; k++) win[k] = *(const u64*)&arow[k*36];
            const u64* wrow = &wsh[(c2*9 + ky*3)*32 + og*4];
            u64 wv[3][4];
            #pragma unroll
            for (int tx = 0; tx < 3; tx++) {
                ulonglong2 p0 = *(const ulonglong2*)&wrow[tx*32];
                ulonglong2 p1 = *(const ulonglong2*)&wrow[tx*32 + 2];
                wv[tx][0] = p0.x; wv[tx][1] = p0.y; wv[tx][2] = p1.x; wv[tx][3] = p1.y;
            }
            #pragma unroll
            for (int xx = 0; xx < 7; xx++)
                #pragma unroll
                for (int tx = 0; tx < 3; tx++)
                    #pragma unroll
                    for (int oo = 0; oo < 4; oo++)
                        ffma2(acc[xx*4+oo], win[xx+tx], wv[tx][oo]);
        }
    }
    #pragma unroll
    for (int oo = 0; oo < 4; oo++) {
        int o = og*4 + oo;
        if (o < 18) {
            float bpv = bp[o];
            #pragma unroll
            for (int xx = 0; xx < 7; xx++)
                g_offs[((b*28+y)*28 + x0+xx)*18 + o] = f2sum(acc[xx*4+oo]) + bpv;
        }
    }
}

// ---------------------------------------------------------------------------
// K3: fused deformable sample + 9pt conv (32->32) + relu + bn2 -> g_h2p
// (unchanged from R8)
// ---------------------------------------------------------------------------
__global__ void k3_deform(const float* __restrict__ w2, const float* __restrict__ g2,
                          const float* __restrict__ b2_, const float* __restrict__ m2,
                          const float* __restrict__ v2) {
    extern __shared__ float sm3[];
    float2* wsh = (float2*)sm3;          // [j*32 + lane]
    float*  xsh = sm3 + 9216;            // [pl*288 + n*32 + c]
    int tid = threadIdx.x;
    int b = blockIdx.x / 14, strip = blockIdx.x % 14;
    int y0 = strip*2;
    for (int i = tid; i < 144*32; i += 256) {
        int lane = i & 31, j = i >> 5;
        int n = j >> 4, c = (2*j) & 31;
        wsh[i] = make_float2(w2[lane*288 + c*9 + n], w2[lane*288 + (c+1)*9 + n]);
    }
    int warp = tid >> 5, lane = tid & 31;
    const float* img = &g_h1p[b*900*32];

    for (int k = 0; k < 7; k++) {
        int pl = warp + k*8;
        int y = y0 + pl/28, x = pl%28;
        const float* offp = &g_offs[((b*28+y)*28+x)*18];
        #pragma unroll
        for (int n = 0; n < 9; n++) {
            float oy = offp[n];
            float ox = offp[9+n];
            float pyr = (float)(y + n/3) + oy;
            float pxr = (float)(x + n%3) + ox;
            float fy = floorf(pyr), fx = floorf(pxr);
            float qy0 = fminf(fmaxf(fy,       0.f), 29.f);
            float qy1 = fminf(fmaxf(fy + 1.f, 0.f), 29.f);
            float qx0 = fminf(fmaxf(fx,       0.f), 29.f);
            float qx1 = fminf(fmaxf(fx + 1.f, 0.f), 29.f);
            float pyc = fminf(fmaxf(pyr, 0.f), 29.f);
            float pxc = fminf(fmaxf(pxr, 0.f), 29.f);
            float glt = (1.f + (qy0 - pyc)) * (1.f + (qx0 - pxc));
            float grb = (1.f - (qy1 - pyc)) * (1.f - (qx1 - pxc));
            float glb = (1.f + (qy0 - pyc)) * (1.f - (qx1 - pxc));
            float grt = (1.f - (qy1 - pyc)) * (1.f + (qx0 - pxc));
            int iy0 = (int)qy0, iy1 = (int)qy1, ix0 = (int)qx0, ix1 = (int)qx1;
            float v00 = img[(iy0*30+ix0)*32 + lane];
            float v11 = img[(iy1*30+ix1)*32 + lane];
            float v01 = img[(iy0*30+ix1)*32 + lane];
            float v10 = img[(iy1*30+ix0)*32 + lane];
            xsh[pl*288 + n*32 + lane] = glt*v00 + grb*v11 + glb*v01 + grt*v10;
        }
    }
    __syncthreads();

    int pbase = warp*7;
    u64 acc2[7] = {0,0,0,0,0,0,0};
    const float* xp0 = &xsh[pbase*288];
    #pragma unroll 2
    for (int j = 0; j < 144; j++) {
        u64 wv = *(const u64*)&wsh[j*32 + lane];
        #pragma unroll
        for (int i = 0; i < 7; i++) {
            u64 a = *(const u64*)(xp0 + i*288 + 2*j);
            ffma2(acc2[i], a, wv);
        }
    }
    float inv = g2[lane] * rsqrtf(v2[lane] + 1e-5f);
    float sh  = b2_[lane] - m2[lane]*inv;
    #pragma unroll
    for (int i = 0; i < 7; i++) {
        int px = pbase + i;
        int y = y0 + px/28, x = px%28;
        g_h2p[((b*30+y+1)*30 + x+1)*32 + lane] = fmaxf(f2sum(acc2[i]), 0.f)*inv + sh;
    }
}

// ---------------------------------------------------------------------------
// K4: conv3(32->64, pad1) + relu + partial pooled sum (bn folded into head)
// block = (image, 4-row strip, o-half via blockIdx.y), 128 thr; warp = row;
// lane = (xg4, og8); thread tile 7px x 4o, c-pair f32x2, lane-distributed.
// dyn smem: wsh u64[16*9*32] (36864B) + ash 6*30*36 floats (25920B) = 62784B
// ---------------------------------------------------------------------------
__global__ void __launch_bounds__(128, 3)
k4_conv3(const float* __restrict__ w3) {
    extern __shared__ float sm4[];
    u64*   wsh = (u64*)sm4;              // [(c2*9+t)*32 + o]
    float* ash = sm4 + 9216;             // [ry][x*36 + c], 6 rows x 30 px
    __shared__ float red[32];
    int tid = threadIdx.x;
    int b = blockIdx.x / 7, strip = blockIdx.x % 7;
    int obase = blockIdx.y * 32;
    for (int i = tid; i < 4608; i += 128) {
        int o = i & 31, t = (i >> 5) % 9, c2 = i / 288;
        const float* wr = &w3[(obase + o)*288];
        ((float2*)wsh)[i] = make_float2(wr[(2*c2)*9 + t], wr[(2*c2+1)*9 + t]);
    }
    const float4* src = (const float4*)&g_h2p[(b*30 + strip*4)*30*32];
    for (int i = tid; i < 6*30*8; i += 128) {
        int q = i & 7, px = (i >> 3) % 30, ry = i / 240;
        *(float4*)&ash[ry*1080 + px*36 + q*4] = src[i];
    }
    if (tid < 32) red[tid] = 0.f;
    __syncthreads();

    int warp = tid >> 5, lane = tid & 31;
    int xg = lane >> 3, og = lane & 7;
    int x0 = xg * 7;
    u64 acc[28];                         // [xx*4 + oo]
    #pragma unroll
    for (int i = 0; i < 28; i++) acc[i] = 0ull;

    #pragma unroll 1
    for (int c2 = 0; c2 < 16; c2++) {
        #pragma unroll
        for (int ky = 0; ky < 3; ky++) {
            const float* arow = &ash[(warp+ky)*1080 + x0*36 + 2*c2];
            u64 win[9];
            #pragma unroll
            for (int k = 0; k < 9; k++) win[k] = *(const u64*)&arow[k*36];
            const u64* wrow = &wsh[(c2*9 + ky*3)*32 + og*4];
            u64 wv[3][4];
            #pragma unroll
            for (int tx = 0; tx < 3; tx++) {
                ulonglong2 p0 = *(const ulonglong2*)&wrow[tx*32];
                ulonglong2 p1 = *(const ulonglong2*)&wrow[tx*32 + 2];
                wv[tx][0] = p0.x; wv[tx][1] = p0.y; wv[tx][2] = p1.x; wv[tx][3] = p1.y;
            }
            #pragma unroll
            for (int xx = 0; xx < 7; xx++)
                #pragma unroll
                for (int tx = 0; tx < 3; tx++)
                    #pragma unroll
                    for (int oo = 0; oo < 4; oo++)
                        ffma2(acc[xx*4+oo], win[xx+tx], wv[tx][oo]);
        }
    }
    #pragma unroll
    for (int oo = 0; oo < 4; oo++) {
        float s = 0.f;
        #pragma unroll
        for (int xx = 0; xx < 7; xx++) s += fmaxf(f2sum(acc[xx*4+oo]), 0.f);
        atomicAdd(&red[og*4 + oo], s);
    }
    __syncthreads();
    if (tid < 32) g_part[(b*7+strip)*64 + obase + tid] = red[tid];
}

// ---------------------------------------------------------------------------
// K5: reduce partials -> mean -> bn3 -> linear(64->10) -> log_softmax
// ---------------------------------------------------------------------------
__global__ void k5_head(const float* __restrict__ g3, const float* __restrict__ b3,
                        const float* __restrict__ m3, const float* __restrict__ v3,
                        const float* __restrict__ wc, const float* __restrict__ bc,
                        float* __restrict__ out) {
    __shared__ float hsh[64];
    __shared__ float lg[10];
    int b = blockIdx.x, tid = threadIdx.x;
    if (tid < 64) {
        float s = 0.f;
        for (int k = 0; k < 7; k++) s += g_part[(b*7+k)*64 + tid];
        s *= (1.f/784.f);
        float inv = g3[tid] * rsqrtf(v3[tid] + 1e-5f);
        hsh[tid] = s * inv + (b3[tid] - m3[tid]*inv);
    }
    __syncthreads();
    if (tid < 10) {
        float acc = bc[tid];
        for (int o = 0; o < 64; o++) acc = fmaf(hsh[o], wc[tid*64 + o], acc);
        lg[tid] = acc;
    }
    __syncthreads();
    if (tid < 10) {
        float mx = -1e30f;
        for (int j = 0; j < 10; j++) mx = fmaxf(mx, lg[j]);
        float se = 0.f;
        for (int j = 0; j < 10; j++) se += expf(lg[j] - mx);
        out[b*10 + tid] = lg[tid] - mx - logf(se);
    }
}

// ---------------------------------------------------------------------------
extern "C" void kernel_launch(void* const* d_in, const int* in_sizes, int n_in,
                              void* d_out, int out_size) {
    const float* x  = (const float*)d_in[0];
    const float* w1 = (const float*)d_in[1];
    const float* g1 = (const float*)d_in[2];
    const float* b1 = (const float*)d_in[3];
    const float* m1 = (const float*)d_in[4];
    const float* v1 = (const float*)d_in[5];
    const float* wp = (const float*)d_in[6];
    const float* bp = (const float*)d_in[7];
    const float* w2 = (const float*)d_in[8];
    const float* g2 = (const float*)d_in[9];
    const float* b2 = (const float*)d_in[10];
    const float* m2 = (const float*)d_in[11];
    const float* v2 = (const float*)d_in[12];
    const float* w3 = (const float*)d_in[13];
    const float* g3 = (const float*)d_in[14];
    const float* b3 = (const float*)d_in[15];
    const float* m3 = (const float*)d_in[16];
    const float* v3 = (const float*)d_in[17];
    const float* wc = (const float*)d_in[18];
    const float* bc = (const float*)d_in[19];

    cudaFuncSetAttribute(k2_pconv,  cudaFuncAttributeMaxDynamicSharedMemorySize, 62784);
    cudaFuncSetAttribute(k3_deform, cudaFuncAttributeMaxDynamicSharedMemorySize, 101376);
    cudaFuncSetAttribute(k4_conv3,  cudaFuncAttributeMaxDynamicSharedMemorySize, 62784);

    k1_conv1<<<BB, 256>>>(x, w1, g1, b1, m1, v1);
    k2_pconv<<<BB*7, 128, 62784>>>(wp, bp);
    k3_deform<<<BB*14, 256, 101376>>>(w2, g2, b2, m2, v2);
    k4_conv3<<<dim3(BB*7, 2), 128, 62784>>>(w3);
    k5_head<<<BB, 64>>>(g3, b3, m3, v3, wc, bc, (float*)d_out);
}

// round 11
// speedup vs baseline: 1.4624x; 1.2506x over previous
#include <cuda_runtime.h>
#include <stdint.h>
#include <math.h>

#define BB 256
#define HH 28
#define WW 28

typedef unsigned long long u64;

// packed f32x2 fma (IEEE identical per lane)
__device__ __forceinline__ void ffma2(u64& acc, u64 a, u64 b) {
    asm("fma.rn.f32x2 %0, %1, %2, %0;" : "+l"(acc) : "l"(a), "l"(b));
}
__device__ __forceinline__ float f2sum(u64 v) {
    float lo, hi;
    asm("mov.b64 {%0, %1}, %2;" : "=f"(lo), "=f"(hi) : "l"(v));
    return lo + hi;
}
__device__ __forceinline__ uint32_t f2tf32(float f) {
    uint32_t r;
    asm("cvt.rna.tf32.f32 %0, %1;" : "=r"(r) : "f"(f));
    return r;
}
// D += A(16x8,row) * B(8x8,col), tf32 in, f32 acc
__device__ __forceinline__ void mma_tf32(float& d0, float& d1, float& d2, float& d3,
                                         uint32_t a0, uint32_t a1, uint32_t a2, uint32_t a3,
                                         uint32_t b0, uint32_t b1) {
    asm("mma.sync.aligned.m16n8k8.row.col.f32.tf32.tf32.f32 "
        "{%0,%1,%2,%3}, {%4,%5,%6,%7}, {%8,%9}, {%0,%1,%2,%3};"
        : "+f"(d0), "+f"(d1), "+f"(d2), "+f"(d3)
        : "r"(a0), "r"(a1), "r"(a2), "r"(a3), "r"(b0), "r"(b1));
}

// Scratch (device globals: allocation-free rule). Zero-initialized at module
// load; padded borders of g_h1p/g_h2p are never written -> stay zero.
__device__ float g_h1p[BB*30*30*32];   // conv1 out, NHWC padded, zero border
__device__ float g_offs[BB*28*28*18];  // p_conv offsets, NHWC
__device__ float g_h2p[BB*30*30*32];   // deform out, NHWC padded, zero border
__device__ float g_part[BB*2*64];      // pooled partial sums of relu(conv3)

// ---------------------------------------------------------------------------
// K1: conv1(3->32, pad1) + relu + bn1 -> g_h1p interior  (unchanged, R9)
// ---------------------------------------------------------------------------
__global__ void k1_conv1(const float* __restrict__ x, const float* __restrict__ w1,
                         const float* __restrict__ g1, const float* __restrict__ b1,
                         const float* __restrict__ m1, const float* __restrict__ v1) {
    __shared__ float xs[3*30*30];
    __shared__ float ws[27*32];
    int tid = threadIdx.x;
    int b = blockIdx.x;
    for (int i = tid; i < 2700; i += 256) xs[i] = 0.f;
    for (int i = tid; i < 27*32; i += 256) {
        int t = i >> 5, o = i & 31;
        ws[i] = w1[o*27 + t];
    }
    __syncthreads();
    for (int i = tid; i < 3*28*28; i += 256) {
        int c = i / 784, rem = i % 784;
        int y = rem / 28, xx = rem % 28;
        xs[c*900 + (y+1)*30 + xx+1] = x[b*2352 + i];
    }
    __syncthreads();

    int warp = tid >> 5, lane = tid & 31;
    float inv = g1[lane] * rsqrtf(v1[lane] + 1e-5f);
    float sh  = b1[lane] - m1[lane]*inv;

    for (int y = warp; y < 28; y += 8) {
        float acc[28];
        #pragma unroll
        for (int i = 0; i < 28; i++) acc[i] = 0.f;
        #pragma unroll
        for (int c = 0; c < 3; c++) {
            #pragma unroll
            for (int ky = 0; ky < 3; ky++) {
                const float* arow = &xs[c*900 + (y+ky)*30];
                float w0 = ws[(c*9+ky*3+0)*32 + lane];
                float w1v = ws[(c*9+ky*3+1)*32 + lane];
                float w2 = ws[(c*9+ky*3+2)*32 + lane];
                float a0 = arow[0], a1 = arow[1];
                #pragma unroll
                for (int xx = 0; xx < 28; xx++) {
                    float a2 = arow[xx+2];
                    acc[xx] = fmaf(a0, w0, acc[xx]);
                    acc[xx] = fmaf(a1, w1v, acc[xx]);
                    acc[xx] = fmaf(a2, w2, acc[xx]);
                    a0 = a1; a1 = a2;
                }
            }
        }
        #pragma unroll
        for (int xx = 0; xx < 28; xx++)
            g_h1p[((b*30+y+1)*30 + xx+1)*32 + lane] = fmaxf(acc[xx], 0.f)*inv + sh;
    }
}

// ---------------------------------------------------------------------------
// K2: p_conv(32->18, pad1) + bias -> g_offs  (unchanged, R9)
// ---------------------------------------------------------------------------
__global__ void __launch_bounds__(128, 3)
k2_pconv(const float* __restrict__ wp, const float* __restrict__ bp) {
    extern __shared__ float sm2[];
    u64*   wsh = (u64*)sm2;
    float* ash = sm2 + 9216;
    int tid = threadIdx.x;
    int b = blockIdx.x / 7, strip = blockIdx.x % 7;
    for (int i = tid; i < 4608; i += 128) {
        int o = i & 31, t = (i >> 5) % 9, c2 = i / 288;
        float lo = 0.f, hi = 0.f;
        if (o < 18) {
            const float* wr = &wp[o*288];
            lo = wr[(2*c2)*9 + t]; hi = wr[(2*c2+1)*9 + t];
        }
        ((float2*)wsh)[i] = make_float2(lo, hi);
    }
    const float4* src = (const float4*)&g_h1p[(b*30 + strip*4)*30*32];
    for (int i = tid; i < 6*30*8; i += 128) {
        int q = i & 7, px = (i >> 3) % 30, ry = i / 240;
        *(float4*)&ash[ry*1080 + px*36 + q*4] = src[i];
    }
    __syncthreads();

    int warp = tid >> 5, lane = tid & 31;
    int xg = lane >> 3, og = lane & 7;
    int x0 = xg * 7;
    int y = strip*4 + warp;
    u64 acc[28];
    #pragma unroll
    for (int i = 0; i < 28; i++) acc[i] = 0ull;

    #pragma unroll 1
    for (int c2 = 0; c2 < 16; c2++) {
        #pragma unroll
        for (int ky = 0; ky < 3; ky++) {
            const float* arow = &ash[(warp+ky)*1080 + x0*36 + 2*c2];
            u64 win[9];
            #pragma unroll
            for (int k = 0; k < 9; k++) win[k] = *(const u64*)&arow[k*36];
            const u64* wrow = &wsh[(c2*9 + ky*3)*32 + og*4];
            u64 wv[3][4];
            #pragma unroll
            for (int tx = 0; tx < 3; tx++) {
                ulonglong2 p0 = *(const ulonglong2*)&wrow[tx*32];
                ulonglong2 p1 = *(const ulonglong2*)&wrow[tx*32 + 2];
                wv[tx][0] = p0.x; wv[tx][1] = p0.y; wv[tx][2] = p1.x; wv[tx][3] = p1.y;
            }
            #pragma unroll
            for (int xx = 0; xx < 7; xx++)
                #pragma unroll
                for (int tx = 0; tx < 3; tx++)
                    #pragma unroll
                    for (int oo = 0; oo < 4; oo++)
                        ffma2(acc[xx*4+oo], win[xx+tx], wv[tx][oo]);
        }
    }
    #pragma unroll
    for (int oo = 0; oo < 4; oo++) {
        int o = og*4 + oo;
        if (o < 18) {
            float bpv = bp[o];
            #pragma unroll
            for (int xx = 0; xx < 7; xx++)
                g_offs[((b*28+y)*28 + x0+xx)*18 + o] = f2sum(acc[xx*4+oo]) + bpv;
        }
    }
}

// ---------------------------------------------------------------------------
// K3: fused deformable sample + 9pt conv (32->32) + relu + bn2  (unchanged R9)
// ---------------------------------------------------------------------------
__global__ void k3_deform(const float* __restrict__ w2, const float* __restrict__ g2,
                          const float* __restrict__ b2_, const float* __restrict__ m2,
                          const float* __restrict__ v2) {
    extern __shared__ float sm3[];
    float2* wsh = (float2*)sm3;
    float*  xsh = sm3 + 9216;
    int tid = threadIdx.x;
    int b = blockIdx.x / 14, strip = blockIdx.x % 14;
    int y0 = strip*2;
    for (int i = tid; i < 144*32; i += 256) {
        int lane = i & 31, j = i >> 5;
        int n = j >> 4, c = (2*j) & 31;
        wsh[i] = make_float2(w2[lane*288 + c*9 + n], w2[lane*288 + (c+1)*9 + n]);
    }
    int warp = tid >> 5, lane = tid & 31;
    const float* img = &g_h1p[b*900*32];

    for (int k = 0; k < 7; k++) {
        int pl = warp + k*8;
        int y = y0 + pl/28, x = pl%28;
        const float* offp = &g_offs[((b*28+y)*28+x)*18];
        #pragma unroll
        for (int n = 0; n < 9; n++) {
            float oy = offp[n];
            float ox = offp[9+n];
            float pyr = (float)(y + n/3) + oy;
            float pxr = (float)(x + n%3) + ox;
            float fy = floorf(pyr), fx = floorf(pxr);
            float qy0 = fminf(fmaxf(fy,       0.f), 29.f);
            float qy1 = fminf(fmaxf(fy + 1.f, 0.f), 29.f);
            float qx0 = fminf(fmaxf(fx,       0.f), 29.f);
            float qx1 = fminf(fmaxf(fx + 1.f, 0.f), 29.f);
            float pyc = fminf(fmaxf(pyr, 0.f), 29.f);
            float pxc = fminf(fmaxf(pxr, 0.f), 29.f);
            float glt = (1.f + (qy0 - pyc)) * (1.f + (qx0 - pxc));
            float grb = (1.f - (qy1 - pyc)) * (1.f - (qx1 - pxc));
            float glb = (1.f + (qy0 - pyc)) * (1.f - (qx1 - pxc));
            float grt = (1.f - (qy1 - pyc)) * (1.f + (qx0 - pxc));
            int iy0 = (int)qy0, iy1 = (int)qy1, ix0 = (int)qx0, ix1 = (int)qx1;
            float v00 = img[(iy0*30+ix0)*32 + lane];
            float v11 = img[(iy1*30+ix1)*32 + lane];
            float v01 = img[(iy0*30+ix1)*32 + lane];
            float v10 = img[(iy1*30+ix0)*32 + lane];
            xsh[pl*288 + n*32 + lane] = glt*v00 + grb*v11 + glb*v01 + grt*v10;
        }
    }
    __syncthreads();

    int pbase = warp*7;
    u64 acc2[7] = {0,0,0,0,0,0,0};
    const float* xp0 = &xsh[pbase*288];
    #pragma unroll 2
    for (int j = 0; j < 144; j++) {
        u64 wv = *(const u64*)&wsh[j*32 + lane];
        #pragma unroll
        for (int i = 0; i < 7; i++) {
            u64 a = *(const u64*)(xp0 + i*288 + 2*j);
            ffma2(acc2[i], a, wv);
        }
    }
    float inv = g2[lane] * rsqrtf(v2[lane] + 1e-5f);
    float sh  = b2_[lane] - m2[lane]*inv;
    #pragma unroll
    for (int i = 0; i < 7; i++) {
        int px = pbase + i;
        int y = y0 + px/28, x = px%28;
        g_h2p[((b*30+y+1)*30 + x+1)*32 + lane] = fmaxf(f2sum(acc2[i]), 0.f)*inv + sh;
    }
}

// ---------------------------------------------------------------------------
// K4: conv3(32->64, pad1) + relu + pooled sum via tf32 mma.sync (tensor pipe)
// block = (image, row-half of 14 rows), 256 thr = 8 warps; warp = 8 outputs.
// 3x3 conv = 9 shifted 1x1 GEMMs accumulated in mma fragments.
// K permutation: fragment col j (step s) <-> channel (j%4)*8 + s + 4*(j>=4),
// so each thread's A data for all 4 k8-steps is channels [q*8, q*8+8) ->
// 4x LDS.128 per tap. B uses the same permutation (held in 72 regs).
// ash: [16 rows][34 px][36 floats] = 78336 B (px 30..33 zero).
// ---------------------------------------------------------------------------
#define ASTR 36
#define AROW (34*ASTR)
__global__ void __launch_bounds__(256, 2)
k4_conv3(const float* __restrict__ w3) {
    extern __shared__ float ash[];
    int tid = threadIdx.x;
    int b = blockIdx.x >> 1, half = blockIdx.x & 1;
    int warp = tid >> 5, lane = tid & 31;
    int gr = lane >> 2, q = lane & 3;
    int y0p = half * 14;

    // zero pad columns (px 30..33 incl. slack)
    for (int i = tid; i < 16*4*ASTR; i += 256) {
        int ry = i / (4*ASTR), r = i % (4*ASTR);
        ash[ry*AROW + 30*ASTR + r] = 0.f;
    }
    // stage acts (tf32-rounded): 16 padded rows x 30 px x 32 c
    const float4* src = (const float4*)&g_h2p[(b*30 + y0p)*30*32];
    for (int i = tid; i < 16*30*8; i += 256) {
        int qq = i & 7, px = (i >> 3) % 30, ry = i / 240;
        float4 v = src[i];
        uint4 t;
        t.x = f2tf32(v.x); t.y = f2tf32(v.y); t.z = f2tf32(v.z); t.w = f2tf32(v.w);
        *(uint4*)&ash[ry*AROW + px*ASTR + qq*4] = t;
    }
    // B fragments in regs: o = warp*8 + gr (col), rows q/q+4 with K-permutation
    uint32_t breg[9][4][2];
    {
        const float* wrow = &w3[(warp*8 + gr)*288];
        #pragma unroll
        for (int t = 0; t < 9; t++)
            #pragma unroll
            for (int s = 0; s < 4; s++) {
                breg[t][s][0] = f2tf32(wrow[(q*8 + s)*9 + t]);
                breg[t][s][1] = f2tf32(wrow[(q*8 + s + 4)*9 + t]);
            }
    }
    __syncthreads();

    float sp0 = 0.f, sp1 = 0.f;
    #pragma unroll 1
    for (int mt = 0; mt < 28; mt++) {
        int ry = mt >> 1, x0 = (mt & 1) << 4;
        float c0 = 0.f, c1 = 0.f, c2 = 0.f, c3 = 0.f;
        #pragma unroll
        for (int t = 0; t < 9; t++) {
            int ky = t/3, kx = t%3;
            const float* base = &ash[(ry+ky)*AROW + (x0+kx)*ASTR + q*8];
            uint4 lo0 = *(const uint4*)&base[gr*ASTR];          // rows gr,   c q*8..+3
            uint4 hi0 = *(const uint4*)&base[gr*ASTR + 4];      // rows gr,   c q*8+4..+7
            uint4 lo1 = *(const uint4*)&base[(gr+8)*ASTR];      // rows gr+8
            uint4 hi1 = *(const uint4*)&base[(gr+8)*ASTR + 4];
            mma_tf32(c0,c1,c2,c3, lo0.x, lo1.x, hi0.x, hi1.x, breg[t][0][0], breg[t][0][1]);
            mma_tf32(c0,c1,c2,c3, lo0.y, lo1.y, hi0.y, hi1.y, breg[t][1][0], breg[t][1][1]);
            mma_tf32(c0,c1,c2,c3, lo0.z, lo1.z, hi0.z, hi1.z, breg[t][2][0], breg[t][2][1]);
            mma_tf32(c0,c1,c2,c3, lo0.w, lo1.w, hi0.w, hi1.w, breg[t][3][0], breg[t][3][1]);
        }
        // pool: c0/c1 at pixel x0+gr (always <28); c2/c3 at x0+gr+8
        sp0 += fmaxf(c0, 0.f);
        sp1 += fmaxf(c1, 0.f);
        if (x0 + gr + 8 < 28) {
            sp0 += fmaxf(c2, 0.f);
            sp1 += fmaxf(c3, 0.f);
        }
    }
    // reduce over gr (lanes differing in bits 2..4)
    #pragma unroll
    for (int off = 4; off < 32; off <<= 1) {
        sp0 += __shfl_xor_sync(0xffffffffu, sp0, off);
        sp1 += __shfl_xor_sync(0xffffffffu, sp1, off);
    }
    if (lane < 4) {
        float* dst = &g_part[(b*2+half)*64 + warp*8 + q*2];
        dst[0] = sp0;
        dst[1] = sp1;
    }
}

// ---------------------------------------------------------------------------
// K5: reduce partials -> mean -> bn3 -> linear(64->10) -> log_softmax
// ---------------------------------------------------------------------------
__global__ void k5_head(const float* __restrict__ g3, const float* __restrict__ b3,
                        const float* __restrict__ m3, const float* __restrict__ v3,
                        const float* __restrict__ wc, const float* __restrict__ bc,
                        float* __restrict__ out) {
    __shared__ float hsh[64];
    __shared__ float lg[10];
    int b = blockIdx.x, tid = threadIdx.x;
    if (tid < 64) {
        float s = g_part[(b*2+0)*64 + tid] + g_part[(b*2+1)*64 + tid];
        s *= (1.f/784.f);
        float inv = g3[tid] * rsqrtf(v3[tid] + 1e-5f);
        hsh[tid] = s * inv + (b3[tid] - m3[tid]*inv);
    }
    __syncthreads();
    if (tid < 10) {
        float acc = bc[tid];
        for (int o = 0; o < 64; o++) acc = fmaf(hsh[o], wc[tid*64 + o], acc);
        lg[tid] = acc;
    }
    __syncthreads();
    if (tid < 10) {
        float mx = -1e30f;
        for (int j = 0; j < 10; j++) mx = fmaxf(mx, lg[j]);
        float se = 0.f;
        for (int j = 0; j < 10; j++) se += expf(lg[j] - mx);
        out[b*10 + tid] = lg[tid] - mx - logf(se);
    }
}

// ---------------------------------------------------------------------------
extern "C" void kernel_launch(void* const* d_in, const int* in_sizes, int n_in,
                              void* d_out, int out_size) {
    const float* x  = (const float*)d_in[0];
    const float* w1 = (const float*)d_in[1];
    const float* g1 = (const float*)d_in[2];
    const float* b1 = (const float*)d_in[3];
    const float* m1 = (const float*)d_in[4];
    const float* v1 = (const float*)d_in[5];
    const float* wp = (const float*)d_in[6];
    const float* bp = (const float*)d_in[7];
    const float* w2 = (const float*)d_in[8];
    const float* g2 = (const float*)d_in[9];
    const float* b2 = (const float*)d_in[10];
    const float* m2 = (const float*)d_in[11];
    const float* v2 = (const float*)d_in[12];
    const float* w3 = (const float*)d_in[13];
    const float* g3 = (const float*)d_in[14];
    const float* b3 = (const float*)d_in[15];
    const float* m3 = (const float*)d_in[16];
    const float* v3 = (const float*)d_in[17];
    const float* wc = (const float*)d_in[18];
    const float* bc = (const float*)d_in[19];

    cudaFuncSetAttribute(k2_pconv,  cudaFuncAttributeMaxDynamicSharedMemorySize, 62784);
    cudaFuncSetAttribute(k3_deform, cudaFuncAttributeMaxDynamicSharedMemorySize, 101376);
    cudaFuncSetAttribute(k4_conv3,  cudaFuncAttributeMaxDynamicSharedMemorySize, 78336);

    k1_conv1<<<BB, 256>>>(x, w1, g1, b1, m1, v1);
    k2_pconv<<<BB*7, 128, 62784>>>(wp, bp);
    k3_deform<<<BB*14, 256, 101376>>>(w2, g2, b2, m2, v2);
    k4_conv3<<<BB*2, 256, 78336>>>(w3);
    k5_head<<<BB, 64>>>(g3, b3, m3, v3, wc, bc, (float*)d_out);
}

// round 12
// speedup vs baseline: 1.8150x; 1.2411x over previous
#include <cuda_runtime.h>
#include <stdint.h>
#include <math.h>

#define BB 256
#define HH 28
#define WW 28

typedef unsigned long long u64;

__device__ __forceinline__ uint32_t f2tf32(float f) {
    uint32_t r;
    asm("cvt.rna.tf32.f32 %0, %1;" : "=r"(r) : "f"(f));
    return r;
}
// D += A(16x8,row) * B(8x8,col), tf32 in, f32 acc
__device__ __forceinline__ void mma_tf32(float& d0, float& d1, float& d2, float& d3,
                                         uint32_t a0, uint32_t a1, uint32_t a2, uint32_t a3,
                                         uint32_t b0, uint32_t b1) {
    asm("mma.sync.aligned.m16n8k8.row.col.f32.tf32.tf32.f32 "
        "{%0,%1,%2,%3}, {%4,%5,%6,%7}, {%8,%9}, {%0,%1,%2,%3};"
        : "+f"(d0), "+f"(d1), "+f"(d2), "+f"(d3)
        : "r"(a0), "r"(a1), "r"(a2), "r"(a3), "r"(b0), "r"(b1));
}

// Scratch (device globals: allocation-free rule). Zero-initialized at module
// load; padded borders of g_h1p/g_h2p are never written -> stay zero.
__device__ float g_h1p[BB*30*30*32];   // conv1 out, NHWC padded, zero border
__device__ float g_offs[BB*28*28*18];  // p_conv offsets, NHWC
__device__ float g_h2p[BB*30*30*32];   // deform out, NHWC padded, zero border
__device__ float g_part[BB*2*64];      // pooled partial sums of relu(conv3)

// ---------------------------------------------------------------------------
// K1: conv1(3->32, pad1) + relu + bn1 -> g_h1p interior  (unchanged)
// ---------------------------------------------------------------------------
__global__ void k1_conv1(const float* __restrict__ x, const float* __restrict__ w1,
                         const float* __restrict__ g1, const float* __restrict__ b1,
                         const float* __restrict__ m1, const float* __restrict__ v1) {
    __shared__ float xs[3*30*30];
    __shared__ float ws[27*32];
    int tid = threadIdx.x;
    int b = blockIdx.x;
    for (int i = tid; i < 2700; i += 256) xs[i] = 0.f;
    for (int i = tid; i < 27*32; i += 256) {
        int t = i >> 5, o = i & 31;
        ws[i] = w1[o*27 + t];
    }
    __syncthreads();
    for (int i = tid; i < 3*28*28; i += 256) {
        int c = i / 784, rem = i % 784;
        int y = rem / 28, xx = rem % 28;
        xs[c*900 + (y+1)*30 + xx+1] = x[b*2352 + i];
    }
    __syncthreads();

    int warp = tid >> 5, lane = tid & 31;
    float inv = g1[lane] * rsqrtf(v1[lane] + 1e-5f);
    float sh  = b1[lane] - m1[lane]*inv;

    for (int y = warp; y < 28; y += 8) {
        float acc[28];
        #pragma unroll
        for (int i = 0; i < 28; i++) acc[i] = 0.f;
        #pragma unroll
        for (int c = 0; c < 3; c++) {
            #pragma unroll
            for (int ky = 0; ky < 3; ky++) {
                const float* arow = &xs[c*900 + (y+ky)*30];
                float w0 = ws[(c*9+ky*3+0)*32 + lane];
                float w1v = ws[(c*9+ky*3+1)*32 + lane];
                float w2 = ws[(c*9+ky*3+2)*32 + lane];
                float a0 = arow[0], a1 = arow[1];
                #pragma unroll
                for (int xx = 0; xx < 28; xx++) {
                    float a2 = arow[xx+2];
                    acc[xx] = fmaf(a0, w0, acc[xx]);
                    acc[xx] = fmaf(a1, w1v, acc[xx]);
                    acc[xx] = fmaf(a2, w2, acc[xx]);
                    a0 = a1; a1 = a2;
                }
            }
        }
        #pragma unroll
        for (int xx = 0; xx < 28; xx++)
            g_h1p[((b*30+y+1)*30 + xx+1)*32 + lane] = fmaxf(acc[xx], 0.f)*inv + sh;
    }
}

// ---------------------------------------------------------------------------
// K2: p_conv(32->18, pad1) + bias -> g_offs, via tf32 mma.
// block = (image, 4-row strip), 256 thr = 8 warps (7 compute).
// GEMM: M = 112 px (7 m-tiles of 16), K = 288 im2col (9 taps x 32c), N = 24
// (o 18..23 zero-padded). Same K-permutation/fragment roles as k4 (verified).
// smem: bsh uint2[4608] (36864B) + ash 6x30x36 tf32 floats (25920B) = 62784B
// ---------------------------------------------------------------------------
__global__ void __launch_bounds__(256, 3)
k2_pconv(const float* __restrict__ wp, const float* __restrict__ bp) {
    extern __shared__ float sm2[];
    uint2* bsh = (uint2*)sm2;            // [((n*4+s)*4+q)*32 + o]
    float* ash = sm2 + 9216;             // [ry][x*36 + c], tf32-rounded
    int tid = threadIdx.x;
    int b = blockIdx.x / 7, strip = blockIdx.x % 7;
    for (int i = tid; i < 4608; i += 256) {
        int o = i & 31, q = (i>>5)&3, s = (i>>7)&3, n = i>>9;
        float lo = 0.f, hi = 0.f;
        if (o < 18) {
            lo = wp[o*288 + (q*8+s)*9 + n];
            hi = wp[o*288 + (q*8+s+4)*9 + n];
        }
        bsh[i] = make_uint2(f2tf32(lo), f2tf32(hi));
    }
    const float4* src = (const float4*)&g_h1p[(b*30 + strip*4)*30*32];
    for (int i = tid; i < 6*30*8; i += 256) {
        int qq = i & 7, px = (i >> 3) % 30, ry = i / 240;
        float4 v = src[i];
        uint4 t4;
        t4.x = f2tf32(v.x); t4.y = f2tf32(v.y); t4.z = f2tf32(v.z); t4.w = f2tf32(v.w);
        *(uint4*)&ash[ry*1080 + px*36 + qq*4] = t4;
    }
    __syncthreads();

    int warp = tid >> 5, lane = tid & 31;
    if (warp >= 7) return;
    int gr = lane >> 2, q = lane & 3;
    int p0 = warp*16 + gr, p1 = p0 + 8;
    int r0 = p0/28, x0 = p0%28, r1 = p1/28, x1 = p1%28;
    float C[3][4];
    #pragma unroll
    for (int t = 0; t < 3; t++)
        #pragma unroll
        for (int j = 0; j < 4; j++) C[t][j] = 0.f;

    #pragma unroll 1
    for (int n = 0; n < 9; n++) {
        int ky = n/3, kx = n%3;
        uint32_t lo0[4], hi0[4], lo1[4], hi1[4];
        const float* a0p = &ash[(r0+ky)*1080 + (x0+kx)*36 + q*8];
        const float* a1p = &ash[(r1+ky)*1080 + (x1+kx)*36 + q*8];
        *(uint4*)lo0 = *(const uint4*)a0p;
        *(uint4*)hi0 = *(const uint4*)(a0p + 4);
        *(uint4*)lo1 = *(const uint4*)a1p;
        *(uint4*)hi1 = *(const uint4*)(a1p + 4);
        #pragma unroll
        for (int s = 0; s < 4; s++) {
            #pragma unroll
            for (int t = 0; t < 3; t++) {
                uint2 bv = bsh[((n*4+s)*4+q)*32 + t*8 + gr];
                mma_tf32(C[t][0], C[t][1], C[t][2], C[t][3],
                         lo0[s], lo1[s], hi0[s], hi1[s], bv.x, bv.y);
            }
        }
    }
    int ybase = strip*4;
    #pragma unroll
    for (int t = 0; t < 3; t++) {
        #pragma unroll
        for (int j = 0; j < 2; j++) {
            int o = t*8 + q*2 + j;
            if (o < 18) {
                float bpv = bp[o];
                g_offs[((b*28 + ybase + r0)*28 + x0)*18 + o] = C[t][j]   + bpv;
                g_offs[((b*28 + ybase + r1)*28 + x1)*18 + o] = C[t][2+j] + bpv;
            }
        }
    }
}

// ---------------------------------------------------------------------------
// K3: fused deformable sample + 9pt conv (32->32) + relu + bn2 -> g_h2p
// Phase A (unchanged sampling math): 8 warps x 7 px -> xsh[64][296] tf32,
// rows 56..63 zeroed. Phase B: tf32 mma GEMM M=64, K=288 (9 kgroups), N=32;
// 8 warps = 4 m-tiles x 2 n-halves.
// smem: bsh uint2[4608] (36864B) + xsh 64*296 floats (75776B) = 112640B
// ---------------------------------------------------------------------------
__global__ void __launch_bounds__(256, 2)
k3_deform(const float* __restrict__ w2, const float* __restrict__ g2,
          const float* __restrict__ b2_, const float* __restrict__ m2,
          const float* __restrict__ v2) {
    extern __shared__ float sm3[];
    uint2* bsh = (uint2*)sm3;            // [((n*4+s)*4+q)*32 + o]
    float* xsh = sm3 + 9216;             // [pl*296 + n*32 + c], tf32 bits
    int tid = threadIdx.x;
    int b = blockIdx.x / 14, strip = blockIdx.x % 14;
    int y0 = strip*2;
    for (int i = tid; i < 4608; i += 256) {
        int o = i & 31, q = (i>>5)&3, s = (i>>7)&3, n = i>>9;
        bsh[i] = make_uint2(f2tf32(w2[o*288 + (q*8+s)*9 + n]),
                            f2tf32(w2[o*288 + (q*8+s+4)*9 + n]));
    }
    for (int i = tid; i < 8*296; i += 256)
        xsh[56*296 + i] = 0.f;

    int warp = tid >> 5, lane = tid & 31;
    const float* img = &g_h1p[b*900*32];

    // Phase A: bilinear sampling (lane = in channel)
    for (int k = 0; k < 7; k++) {
        int pl = warp + k*8;             // 0..55
        int y = y0 + pl/28, x = pl%28;
        const float* offp = &g_offs[((b*28+y)*28+x)*18];
        #pragma unroll
        for (int n = 0; n < 9; n++) {
            float oy = offp[n];
            float ox = offp[9+n];
            float pyr = (float)(y + n/3) + oy;
            float pxr = (float)(x + n%3) + ox;
            float fy = floorf(pyr), fx = floorf(pxr);
            float qy0 = fminf(fmaxf(fy,       0.f), 29.f);
            float qy1 = fminf(fmaxf(fy + 1.f, 0.f), 29.f);
            float qx0 = fminf(fmaxf(fx,       0.f), 29.f);
            float qx1 = fminf(fmaxf(fx + 1.f, 0.f), 29.f);
            float pyc = fminf(fmaxf(pyr, 0.f), 29.f);
            float pxc = fminf(fmaxf(pxr, 0.f), 29.f);
            float glt = (1.f + (qy0 - pyc)) * (1.f + (qx0 - pxc));
            float grb = (1.f - (qy1 - pyc)) * (1.f - (qx1 - pxc));
            float glb = (1.f + (qy0 - pyc)) * (1.f - (qx1 - pxc));
            float grt = (1.f - (qy1 - pyc)) * (1.f + (qx0 - pxc));
            int iy0 = (int)qy0, iy1 = (int)qy1, ix0 = (int)qx0, ix1 = (int)qx1;
            float v00 = img[(iy0*30+ix0)*32 + lane];
            float v11 = img[(iy1*30+ix1)*32 + lane];
            float v01 = img[(iy0*30+ix1)*32 + lane];
            float v10 = img[(iy1*30+ix0)*32 + lane];
            float val = glt*v00 + grb*v11 + glb*v01 + grt*v10;
            xsh[pl*296 + n*32 + lane] = __uint_as_float(f2tf32(val));
        }
    }
    __syncthreads();

    // Phase B: M=64 x K=288 x N=32 via mma
    int mt = warp >> 1;
    int nb = (warp & 1) * 16;
    int gr = lane >> 2, q = lane & 3;
    float C0[4] = {0,0,0,0}, C1[4] = {0,0,0,0};
    const float* abase0 = &xsh[(mt*16 + gr)*296 + q*8];
    const float* abase1 = abase0 + 8*296;
    #pragma unroll 1
    for (int n = 0; n < 9; n++) {
        uint32_t lo0[4], hi0[4], lo1[4], hi1[4];
        *(uint4*)lo0 = *(const uint4*)&abase0[n*32];
        *(uint4*)hi0 = *(const uint4*)&abase0[n*32 + 4];
        *(uint4*)lo1 = *(const uint4*)&abase1[n*32];
        *(uint4*)hi1 = *(const uint4*)&abase1[n*32 + 4];
        #pragma unroll
        for (int s = 0; s < 4; s++) {
            uint2 bv0 = bsh[((n*4+s)*4+q)*32 + nb + gr];
            uint2 bv1 = bsh[((n*4+s)*4+q)*32 + nb + 8 + gr];
            mma_tf32(C0[0], C0[1], C0[2], C0[3],
                     lo0[s], lo1[s], hi0[s], hi1[s], bv0.x, bv0.y);
            mma_tf32(C1[0], C1[1], C1[2], C1[3],
                     lo0[s], lo1[s], hi0[s], hi1[s], bv1.x, bv1.y);
        }
    }
    int pl0 = mt*16 + gr;
    int pl1 = pl0 + 8;
    #pragma unroll
    for (int t = 0; t < 2; t++) {
        const float* Cp = t ? C1 : C0;
        #pragma unroll
        for (int j = 0; j < 2; j++) {
            int o = nb + t*8 + q*2 + j;
            float inv = g2[o] * rsqrtf(v2[o] + 1e-5f);
            float sh  = b2_[o] - m2[o]*inv;
            {
                int y = y0 + pl0/28, x = pl0%28;
                g_h2p[((b*30+y+1)*30 + x+1)*32 + o] = fmaxf(Cp[j], 0.f)*inv + sh;
            }
            if (pl1 < 56) {
                int y = y0 + pl1/28, x = pl1%28;
                g_h2p[((b*30+y+1)*30 + x+1)*32 + o] = fmaxf(Cp[2+j], 0.f)*inv + sh;
            }
        }
    }
}

// ---------------------------------------------------------------------------
// K4: conv3(32->64, pad1) + relu + pooled sum via tf32 mma  (unchanged, R11)
// ---------------------------------------------------------------------------
#define ASTR 36
#define AROW (34*ASTR)
__global__ void __launch_bounds__(256, 2)
k4_conv3(const float* __restrict__ w3) {
    extern __shared__ float ash[];
    int tid = threadIdx.x;
    int b = blockIdx.x >> 1, half = blockIdx.x & 1;
    int warp = tid >> 5, lane = tid & 31;
    int gr = lane >> 2, q = lane & 3;
    int y0p = half * 14;

    for (int i = tid; i < 16*4*ASTR; i += 256) {
        int ry = i / (4*ASTR), r = i % (4*ASTR);
        ash[ry*AROW + 30*ASTR + r] = 0.f;
    }
    const float4* src = (const float4*)&g_h2p[(b*30 + y0p)*30*32];
    for (int i = tid; i < 16*30*8; i += 256) {
        int qq = i & 7, px = (i >> 3) % 30, ry = i / 240;
        float4 v = src[i];
        uint4 t;
        t.x = f2tf32(v.x); t.y = f2tf32(v.y); t.z = f2tf32(v.z); t.w = f2tf32(v.w);
        *(uint4*)&ash[ry*AROW + px*ASTR + qq*4] = t;
    }
    uint32_t breg[9][4][2];
    {
        const float* wrow = &w3[(warp*8 + gr)*288];
        #pragma unroll
        for (int t = 0; t < 9; t++)
            #pragma unroll
            for (int s = 0; s < 4; s++) {
                breg[t][s][0] = f2tf32(wrow[(q*8 + s)*9 + t]);
                breg[t][s][1] = f2tf32(wrow[(q*8 + s + 4)*9 + t]);
            }
    }
    __syncthreads();

    float sp0 = 0.f, sp1 = 0.f;
    #pragma unroll 1
    for (int mt = 0; mt < 28; mt++) {
        int ry = mt >> 1, x0 = (mt & 1) << 4;
        float c0 = 0.f, c1 = 0.f, c2 = 0.f, c3 = 0.f;
        #pragma unroll
        for (int t = 0; t < 9; t++) {
            int ky = t/3, kx = t%3;
            const float* base = &ash[(ry+ky)*AROW + (x0+kx)*ASTR + q*8];
            uint4 lo0 = *(const uint4*)&base[gr*ASTR];
            uint4 hi0 = *(const uint4*)&base[gr*ASTR + 4];
            uint4 lo1 = *(const uint4*)&base[(gr+8)*ASTR];
            uint4 hi1 = *(const uint4*)&base[(gr+8)*ASTR + 4];
            mma_tf32(c0,c1,c2,c3, lo0.x, lo1.x, hi0.x, hi1.x, breg[t][0][0], breg[t][0][1]);
            mma_tf32(c0,c1,c2,c3, lo0.y, lo1.y, hi0.y, hi1.y, breg[t][1][0], breg[t][1][1]);
            mma_tf32(c0,c1,c2,c3, lo0.z, lo1.z, hi0.z, hi1.z, breg[t][2][0], breg[t][2][1]);
            mma_tf32(c0,c1,c2,c3, lo0.w, lo1.w, hi0.w, hi1.w, breg[t][3][0], breg[t][3][1]);
        }
        sp0 += fmaxf(c0, 0.f);
        sp1 += fmaxf(c1, 0.f);
        if (x0 + gr + 8 < 28) {
            sp0 += fmaxf(c2, 0.f);
            sp1 += fmaxf(c3, 0.f);
        }
    }
    #pragma unroll
    for (int off = 4; off < 32; off <<= 1) {
        sp0 += __shfl_xor_sync(0xffffffffu, sp0, off);
        sp1 += __shfl_xor_sync(0xffffffffu, sp1, off);
    }
    if (lane < 4) {
        float* dst = &g_part[(b*2+half)*64 + warp*8 + q*2];
        dst[0] = sp0;
        dst[1] = sp1;
    }
}

// ---------------------------------------------------------------------------
// K5: reduce partials -> mean -> bn3 -> linear(64->10) -> log_softmax
// ---------------------------------------------------------------------------
__global__ void k5_head(const float* __restrict__ g3, const float* __restrict__ b3,
                        const float* __restrict__ m3, const float* __restrict__ v3,
                        const float* __restrict__ wc, const float* __restrict__ bc,
                        float* __restrict__ out) {
    __shared__ float hsh[64];
    __shared__ float lg[10];
    int b = blockIdx.x, tid = threadIdx.x;
    if (tid < 64) {
        float s = g_part[(b*2+0)*64 + tid] + g_part[(b*2+1)*64 + tid];
        s *= (1.f/784.f);
        float inv = g3[tid] * rsqrtf(v3[tid] + 1e-5f);
        hsh[tid] = s * inv + (b3[tid] - m3[tid]*inv);
    }
    __syncthreads();
    if (tid < 10) {
        float acc = bc[tid];
        for (int o = 0; o < 64; o++) acc = fmaf(hsh[o], wc[tid*64 + o], acc);
        lg[tid] = acc;
    }
    __syncthreads();
    if (tid < 10) {
        float mx = -1e30f;
        for (int j = 0; j < 10; j++) mx = fmaxf(mx, lg[j]);
        float se = 0.f;
        for (int j = 0; j < 10; j++) se += expf(lg[j] - mx);
        out[b*10 + tid] = lg[tid] - mx - logf(se);
    }
}

// ---------------------------------------------------------------------------
extern "C" void kernel_launch(void* const* d_in, const int* in_sizes, int n_in,
                              void* d_out, int out_size) {
    const float* x  = (const float*)d_in[0];
    const float* w1 = (const float*)d_in[1];
    const float* g1 = (const float*)d_in[2];
    const float* b1 = (const float*)d_in[3];
    const float* m1 = (const float*)d_in[4];
    const float* v1 = (const float*)d_in[5];
    const float* wp = (const float*)d_in[6];
    const float* bp = (const float*)d_in[7];
    const float* w2 = (const float*)d_in[8];
    const float* g2 = (const float*)d_in[9];
    const float* b2 = (const float*)d_in[10];
    const float* m2 = (const float*)d_in[11];
    const float* v2 = (const float*)d_in[12];
    const float* w3 = (const float*)d_in[13];
    const float* g3 = (const float*)d_in[14];
    const float* b3 = (const float*)d_in[15];
    const float* m3 = (const float*)d_in[16];
    const float* v3 = (const float*)d_in[17];
    const float* wc = (const float*)d_in[18];
    const float* bc = (const float*)d_in[19];

    cudaFuncSetAttribute(k2_pconv,  cudaFuncAttributeMaxDynamicSharedMemorySize, 62784);
    cudaFuncSetAttribute(k3_deform, cudaFuncAttributeMaxDynamicSharedMemorySize, 112640);
    cudaFuncSetAttribute(k4_conv3,  cudaFuncAttributeMaxDynamicSharedMemorySize, 78336);

    k1_conv1<<<BB, 256>>>(x, w1, g1, b1, m1, v1);
    k2_pconv<<<BB*7, 256, 62784>>>(wp, bp);
    k3_deform<<<BB*14, 256, 112640>>>(w2, g2, b2, m2, v2);
    k4_conv3<<<BB*2, 256, 78336>>>(w3);
    k5_head<<<BB, 64>>>(g3, b3, m3, v3, wc, bc, (float*)d_out);
}